// round 1
// baseline (speedup 1.0000x reference)
#include <cuda_runtime.h>
#include <math.h>

// ---------------- problem constants ----------------
#define N_NODES 16384
#define B_GR    64
#define NPG     256
#define E_EDGES 524288
#define F_IN    32
#define D_IN    56        // 32 + 3*8
#define W       256
#define S       257
#define HEADS   8
#define DH      32
#define DFF     1024
#define HID     512
#define OUT_D   64
#define LAYERS  2
#define MROWS   (B_GR * S)   // 16448
#define MPAD    16512        // 129 * 128

// ---------------- scratch (device globals; no allocs) ----------------
__device__ float g_xc  [N_NODES * D_IN];
__device__ float g_agg [N_NODES * D_IN];
__device__ float g_deg [N_NODES];
__device__ float g_xd  [MPAD * W];
__device__ float g_h1  [MPAD * W];
__device__ float g_qkv [MPAD * 3 * W];
__device__ float g_attn[MPAD * W];
__device__ float g_ff  [MPAD * DFF];

// ---------------- helpers ----------------
__device__ __forceinline__ float warp_sum(float v) {
#pragma unroll
    for (int o = 16; o > 0; o >>= 1) v += __shfl_xor_sync(0xffffffffu, v, o);
    return v;
}
__device__ __forceinline__ float warp_max(float v) {
#pragma unroll
    for (int o = 16; o > 0; o >>= 1) v = fmaxf(v, __shfl_xor_sync(0xffffffffu, v, o));
    return v;
}
// block-wide reductions for blockDim.x == 256 (8 warps)
__device__ __forceinline__ float block_sum256(float v, float* red) {
    __syncthreads();
    v = warp_sum(v);
    if ((threadIdx.x & 31) == 0) red[threadIdx.x >> 5] = v;
    __syncthreads();
    float r = 0.f;
#pragma unroll
    for (int i = 0; i < 8; i++) r += red[i];
    return r;
}
__device__ __forceinline__ float block_max256(float v, float* red) {
    __syncthreads();
    v = warp_max(v);
    if ((threadIdx.x & 31) == 0) red[threadIdx.x >> 5] = v;
    __syncthreads();
    float r = -1e30f;
#pragma unroll
    for (int i = 0; i < 8; i++) r = fmaxf(r, red[i]);
    return r;
}
__device__ __forceinline__ float gelu_f(float x) {
    float u = 0.7978845608028654f * (x + 0.044715f * x * x * x);
    float t;
    asm("tanh.approx.f32 %0, %1;" : "=f"(t) : "f"(u));
    return 0.5f * x * (1.0f + t);
}

// ---------------- stage 1: positional encoding + concat ----------------
__global__ void k_pe(const float* __restrict__ x, const float* __restrict__ p) {
    int i = blockIdx.x * blockDim.x + threadIdx.x;
    if (i >= N_NODES * D_IN) return;
    int n = i / D_IN, j = i - n * D_IN;
    float v;
    if (j < F_IN) {
        v = x[n * F_IN + j];
    } else {
        int jj = j - F_IN;
        int d = jj >> 3, f = jj & 7;
        float freq = 3.14159265358979323846f * (float)(1 << f);
        v = sinf(p[n * 3 + d] * freq);
    }
    g_xc[i] = v;
}

// ---------------- stage 2: degree / scatter ----------------
__global__ void k_deg_init() {
    int n = blockIdx.x * blockDim.x + threadIdx.x;
    if (n < N_NODES) g_deg[n] = 1.0f;  // self loop
}
__global__ void k_deg_count(const int* __restrict__ ei) {
    int e = blockIdx.x * blockDim.x + threadIdx.x;
    if (e < E_EDGES) atomicAdd(&g_deg[ei[E_EDGES + e]], 1.0f);
}
__global__ void k_dinv() {
    int n = blockIdx.x * blockDim.x + threadIdx.x;
    if (n < N_NODES) g_deg[n] = rsqrtf(fmaxf(g_deg[n], 1e-12f));
}
__global__ void k_agg_init() {
    int i = blockIdx.x * blockDim.x + threadIdx.x;
    if (i >= N_NODES * D_IN) return;
    int n = i / D_IN;
    float d = g_deg[n];
    g_agg[i] = d * d * g_xc[i];
}
// one edge handled by 64 threads (56 active)
__global__ void k_scatter(const int* __restrict__ ei) {
    int i = blockIdx.x * blockDim.x + threadIdx.x;  // E*64 total
    int e = i >> 6, j = i & 63;
    if (j >= D_IN) return;
    int r = ei[e];
    int c = ei[E_EDGES + e];
    float coef = g_deg[r] * g_deg[c];
    atomicAdd(&g_agg[c * D_IN + j], coef * g_xc[r * D_IN + j]);
}

// ---------------- stage 3: GCN matmul + bias + ln_pre, scatter to dense ----------------
__global__ void __launch_bounds__(256) k_gcn(const float* __restrict__ w,
                                             const float* __restrict__ bias,
                                             const float* __restrict__ lns,
                                             const float* __restrict__ lnb) {
    int n = blockIdx.x;
    int t = threadIdx.x;
    __shared__ float a[D_IN];
    __shared__ float red[8];
    if (t < D_IN) a[t] = g_agg[n * D_IN + t];
    __syncthreads();
    float acc = bias[t];
#pragma unroll
    for (int i = 0; i < D_IN; i++) acc += a[i] * w[i * W + t];
    float s1 = block_sum256(acc, red);
    float s2 = block_sum256(acc * acc, red);
    float m = s1 * (1.0f / W);
    float var = s2 * (1.0f / W) - m * m;
    float o = (acc - m) * rsqrtf(var + 1e-5f) * lns[t] + lnb[t];
    int b = n / NPG, pos = n - b * NPG;
    g_xd[(size_t)(b * S + pos + 1) * W + t] = o;
}
__global__ void __launch_bounds__(256) k_cls(const float* __restrict__ cls,
                                             const float* __restrict__ lns,
                                             const float* __restrict__ lnb) {
    int t = threadIdx.x;
    __shared__ float red[8];
    float v = cls[t];
    float s1 = block_sum256(v, red);
    float s2 = block_sum256(v * v, red);
    float m = s1 * (1.0f / W);
    float var = s2 * (1.0f / W) - m * m;
    float o = (v - m) * rsqrtf(var + 1e-5f) * lns[t] + lnb[t];
    g_xd[(size_t)blockIdx.x * S * W + t] = o;
}

// ---------------- LayerNorm rows: g_xd -> g_h1 ----------------
__global__ void __launch_bounds__(256) k_ln(const float* __restrict__ s,
                                            const float* __restrict__ b) {
    int row = blockIdx.x, t = threadIdx.x;
    __shared__ float red[8];
    float v = g_xd[(size_t)row * W + t];
    float s1 = block_sum256(v, red);
    float s2 = block_sum256(v * v, red);
    float m = s1 * (1.0f / W);
    float var = s2 * (1.0f / W) - m * m;
    g_h1[(size_t)row * W + t] = (v - m) * rsqrtf(var + 1e-5f) * s[t] + b[t];
}

// ---------------- generic fp32 GEMM: C = [res +] act(A*B + bias) ----------------
// A[M,K] row-major, B[K,N] row-major. M multiple of 128, N multiple of 128, K multiple of 8.
#define BM 128
#define BN 128
#define BK 8
__global__ void __launch_bounds__(256) k_gemm(const float* __restrict__ A,
                                              const float* __restrict__ Bw,
                                              const float* __restrict__ bias,
                                              const float* __restrict__ Res,
                                              float* __restrict__ C,
                                              int K, int Nn, int act, int has_res) {
    __shared__ float As[BK][BM + 4];
    __shared__ float Bs[BK][BN + 4];
    int bm = blockIdx.y * BM, bn = blockIdx.x * BN;
    int t = threadIdx.x;
    int tx = t & 15, ty = t >> 4;

    float acc[8][8];
#pragma unroll
    for (int i = 0; i < 8; i++)
#pragma unroll
        for (int j = 0; j < 8; j++) acc[i][j] = 0.f;

    int arow = t >> 1, akq = (t & 1) * 4;
    int brow = t >> 5, bcol = (t & 31) * 4;
    const float* Ap = A + (size_t)(bm + arow) * K + akq;
    const float* Bp = Bw + (size_t)brow * Nn + bn + bcol;

    for (int k0 = 0; k0 < K; k0 += BK) {
        float4 av = *(const float4*)(Ap + k0);
        float4 bv = *(const float4*)(Bp + (size_t)k0 * Nn);
        As[akq + 0][arow] = av.x;
        As[akq + 1][arow] = av.y;
        As[akq + 2][arow] = av.z;
        As[akq + 3][arow] = av.w;
        *(float4*)&Bs[brow][bcol] = bv;
        __syncthreads();
#pragma unroll
        for (int kk = 0; kk < BK; kk++) {
            float a[8], b[8];
            float4 a0 = *(const float4*)&As[kk][ty * 8];
            float4 a1 = *(const float4*)&As[kk][ty * 8 + 4];
            float4 b0 = *(const float4*)&Bs[kk][tx * 8];
            float4 b1 = *(const float4*)&Bs[kk][tx * 8 + 4];
            a[0]=a0.x; a[1]=a0.y; a[2]=a0.z; a[3]=a0.w;
            a[4]=a1.x; a[5]=a1.y; a[6]=a1.z; a[7]=a1.w;
            b[0]=b0.x; b[1]=b0.y; b[2]=b0.z; b[3]=b0.w;
            b[4]=b1.x; b[5]=b1.y; b[6]=b1.z; b[7]=b1.w;
#pragma unroll
            for (int i = 0; i < 8; i++)
#pragma unroll
                for (int j = 0; j < 8; j++) acc[i][j] += a[i] * b[j];
        }
        __syncthreads();
    }
#pragma unroll
    for (int i = 0; i < 8; i++) {
        int row = bm + ty * 8 + i;
#pragma unroll
        for (int j = 0; j < 8; j++) {
            int col = bn + tx * 8 + j;
            float v = acc[i][j] + bias[col];
            if (act == 1) v = gelu_f(v);
            if (has_res) v += Res[(size_t)row * Nn + col];
            C[(size_t)row * Nn + col] = v;
        }
    }
}

// ---------------- attention (one block per (b,h)) ----------------
__global__ void __launch_bounds__(256) k_attn() {
    extern __shared__ float sm[];
    float* Ks = sm;                  // S*33
    float* Vs = Ks + S * 33;         // S*33
    float* sc = Vs + S * 33;         // S
    float* part = sc + S;            // 256
    __shared__ float qv[DH];
    __shared__ float red[8];

    int bh = blockIdx.x;
    int b = bh >> 3, h = bh & 7;
    int t = threadIdx.x;
    const float* base = g_qkv + (size_t)b * S * (3 * W);

    for (int idx = t; idx < S * DH; idx += 256) {
        int s_ = idx >> 5, d = idx & 31;
        Ks[s_ * 33 + d] = base[(size_t)s_ * 768 + 256 + h * 32 + d];
        Vs[s_ * 33 + d] = base[(size_t)s_ * 768 + 512 + h * 32 + d];
    }
    __syncthreads();

    const float scale = 0.17677669529663687f;  // 1/sqrt(32)
    for (int q = 0; q < S; q++) {
        if (t < DH) qv[t] = base[(size_t)q * 768 + h * 32 + t];
        __syncthreads();
        float lmax = -1e30f;
        for (int k = t; k < S; k += 256) {
            float s = 0.f;
#pragma unroll
            for (int d = 0; d < DH; d++) s += qv[d] * Ks[k * 33 + d];
            s *= scale;
            if (q > 0 && k > q) s = -1e9f;
            sc[k] = s;
            lmax = fmaxf(lmax, s);
        }
        float m = block_max256(lmax, red);
        float lsum = 0.f;
        for (int k = t; k < S; k += 256) {
            float e = __expf(sc[k] - m);
            sc[k] = e;
            lsum += e;
        }
        float ssum = block_sum256(lsum, red);
        float inv = 1.0f / ssum;
        __syncthreads();  // sc[] fully written & visible
        int d = t & 31, g = t >> 5;
        float accv = 0.f;
        for (int k = g; k < S; k += 8) accv += sc[k] * Vs[k * 33 + d];
        part[t] = accv;
        __syncthreads();
        if (t < DH) {
            float o = 0.f;
#pragma unroll
            for (int g2 = 0; g2 < 8; g2++) o += part[g2 * 32 + t];
            g_attn[((size_t)b * S + q) * W + h * 32 + t] = o * inv;
        }
        __syncthreads();
    }
}

// ---------------- decoder (fused, one block per graph) ----------------
__global__ void __launch_bounds__(256) k_dec(const float* __restrict__ lns,
                                             const float* __restrict__ lnb,
                                             const float* __restrict__ w1,
                                             const float* __restrict__ b1,
                                             const float* __restrict__ w2,
                                             const float* __restrict__ b2,
                                             const float* __restrict__ w3,
                                             const float* __restrict__ b3,
                                             float* __restrict__ outp) {
    int b = blockIdx.x, t = threadIdx.x;
    __shared__ float cls[W];
    __shared__ float h1[HID];
    __shared__ float h2[HID];
    __shared__ float red[8];
    float v = g_xd[(size_t)b * S * W + t];
    float s1 = block_sum256(v, red);
    float s2 = block_sum256(v * v, red);
    float m = s1 * (1.0f / W);
    float var = s2 * (1.0f / W) - m * m;
    cls[t] = (v - m) * rsqrtf(var + 1e-5f) * lns[t] + lnb[t];
    __syncthreads();
    for (int j = t; j < HID; j += 256) {
        float a = b1[j];
#pragma unroll 8
        for (int i = 0; i < W; i++) a += cls[i] * w1[i * HID + j];
        h1[j] = fmaxf(a, 0.f);
    }
    __syncthreads();
    for (int j = t; j < HID; j += 256) {
        float a = b2[j];
#pragma unroll 8
        for (int i = 0; i < HID; i++) a += h1[i] * w2[i * HID + j];
        h2[j] = fmaxf(a, 0.f);
    }
    __syncthreads();
    if (t < OUT_D) {
        float a = b3[t];
#pragma unroll 8
        for (int i = 0; i < HID; i++) a += h2[i] * w3[i * OUT_D + t];
        outp[b * OUT_D + t] = fmaxf(a, 0.f);
    }
}

// ---------------- launch ----------------
extern "C" void kernel_launch(void* const* d_in, const int* in_sizes, int n_in,
                              void* d_out, int out_size) {
    const float* x          = (const float*)d_in[0];
    const float* p          = (const float*)d_in[1];
    const int*   edge_index = (const int*)d_in[2];
    // d_in[3] = batch (structure is known: arange(N)//NPG) — unused
    const float* gcn_w      = (const float*)d_in[4];
    const float* gcn_b      = (const float*)d_in[5];
    const float* cls_token  = (const float*)d_in[6];
    const float* ln_pre_s   = (const float*)d_in[7];
    const float* ln_pre_b   = (const float*)d_in[8];
    const float* norm1_s    = (const float*)d_in[9];
    const float* norm1_b    = (const float*)d_in[10];
    const float* in_proj_w  = (const float*)d_in[11];
    const float* in_proj_b  = (const float*)d_in[12];
    const float* out_proj_w = (const float*)d_in[13];
    const float* out_proj_b = (const float*)d_in[14];
    const float* norm2_s    = (const float*)d_in[15];
    const float* norm2_b    = (const float*)d_in[16];
    const float* ff_w1      = (const float*)d_in[17];
    const float* ff_b1      = (const float*)d_in[18];
    const float* ff_w2      = (const float*)d_in[19];
    const float* ff_b2      = (const float*)d_in[20];
    const float* ln_post_s  = (const float*)d_in[21];
    const float* ln_post_b  = (const float*)d_in[22];
    const float* dec_w1     = (const float*)d_in[23];
    const float* dec_b1     = (const float*)d_in[24];
    const float* dec_w2     = (const float*)d_in[25];
    const float* dec_b2     = (const float*)d_in[26];
    const float* dec_w3     = (const float*)d_in[27];
    const float* dec_b3     = (const float*)d_in[28];
    float* out = (float*)d_out;

    float *p_h1, *p_qkv, *p_attn, *p_ff, *p_xd;
    cudaGetSymbolAddress((void**)&p_h1, g_h1);
    cudaGetSymbolAddress((void**)&p_qkv, g_qkv);
    cudaGetSymbolAddress((void**)&p_attn, g_attn);
    cudaGetSymbolAddress((void**)&p_ff, g_ff);
    cudaGetSymbolAddress((void**)&p_xd, g_xd);

    const int attn_smem = (2 * S * 33 + S + 256) * 4;
    cudaFuncSetAttribute(k_attn, cudaFuncAttributeMaxDynamicSharedMemorySize, attn_smem);

    // GCN front-end
    k_pe<<<(N_NODES * D_IN + 255) / 256, 256>>>(x, p);
    k_deg_init<<<(N_NODES + 255) / 256, 256>>>();
    k_deg_count<<<E_EDGES / 256, 256>>>(edge_index);
    k_dinv<<<(N_NODES + 255) / 256, 256>>>();
    k_agg_init<<<(N_NODES * D_IN + 255) / 256, 256>>>();
    k_scatter<<<(E_EDGES * 64) / 256, 256>>>(edge_index);
    k_gcn<<<N_NODES, 256>>>(gcn_w, gcn_b, ln_pre_s, ln_pre_b);
    k_cls<<<B_GR, 256>>>(cls_token, ln_pre_s, ln_pre_b);

    // transformer layers
    for (int l = 0; l < LAYERS; l++) {
        k_ln<<<MROWS, 256>>>(norm1_s + l * W, norm1_b + l * W);
        k_gemm<<<dim3(768 / BN, MPAD / BM), 256>>>(p_h1, in_proj_w + (size_t)l * W * 3 * W,
                                                   in_proj_b + l * 3 * W, nullptr, p_qkv,
                                                   W, 3 * W, 0, 0);
        k_attn<<<B_GR * HEADS, 256, attn_smem>>>();
        k_gemm<<<dim3(W / BN, MPAD / BM), 256>>>(p_attn, out_proj_w + (size_t)l * W * W,
                                                 out_proj_b + l * W, p_xd, p_xd,
                                                 W, W, 0, 1);
        k_ln<<<MROWS, 256>>>(norm2_s + l * W, norm2_b + l * W);
        k_gemm<<<dim3(DFF / BN, MPAD / BM), 256>>>(p_h1, ff_w1 + (size_t)l * W * DFF,
                                                   ff_b1 + l * DFF, nullptr, p_ff,
                                                   W, DFF, 1, 0);
        k_gemm<<<dim3(W / BN, MPAD / BM), 256>>>(p_ff, ff_w2 + (size_t)l * DFF * W,
                                                 ff_b2 + l * W, p_xd, p_xd,
                                                 DFF, W, 1, 1);
    }

    // decoder on cls rows
    k_dec<<<B_GR, 256>>>(ln_post_s, ln_post_b, dec_w1, dec_b1, dec_w2, dec_b2,
                         dec_w3, dec_b3, out);
    (void)in_sizes; (void)n_in; (void)out_size;
}

// round 2
// speedup vs baseline: 1.0649x; 1.0649x over previous
#include <cuda_runtime.h>
#include <math.h>

// ---------------- problem constants ----------------
#define N_NODES 16384
#define B_GR    64
#define NPG     256
#define E_EDGES 524288
#define F_IN    32
#define D_IN    56        // 32 + 3*8
#define W       256
#define S       257
#define HEADS   8
#define DH      32
#define DFF     1024
#define HID     512
#define OUT_D   64
#define LAYERS  2
#define MROWS   (B_GR * S)   // 16448
#define MPAD    16512        // 129 * 128

// ---------------- scratch (device globals; no allocs) ----------------
__device__ float g_xc  [N_NODES * D_IN];
__device__ float g_agg [N_NODES * D_IN];
__device__ float g_deg [N_NODES];
__device__ float g_xd  [MPAD * W];
__device__ float g_h1  [MPAD * W];
__device__ float g_qkv [MPAD * 3 * W];
__device__ float g_attn[MPAD * W];
__device__ float g_ff  [MPAD * DFF];

// ---------------- helpers ----------------
__device__ __forceinline__ float warp_sum(float v) {
#pragma unroll
    for (int o = 16; o > 0; o >>= 1) v += __shfl_xor_sync(0xffffffffu, v, o);
    return v;
}
__device__ __forceinline__ float warp_max(float v) {
#pragma unroll
    for (int o = 16; o > 0; o >>= 1) v = fmaxf(v, __shfl_xor_sync(0xffffffffu, v, o));
    return v;
}
__device__ __forceinline__ float block_sum256(float v, float* red) {
    __syncthreads();
    v = warp_sum(v);
    if ((threadIdx.x & 31) == 0) red[threadIdx.x >> 5] = v;
    __syncthreads();
    float r = 0.f;
#pragma unroll
    for (int i = 0; i < 8; i++) r += red[i];
    return r;
}
__device__ __forceinline__ float block_max256(float v, float* red) {
    __syncthreads();
    v = warp_max(v);
    if ((threadIdx.x & 31) == 0) red[threadIdx.x >> 5] = v;
    __syncthreads();
    float r = -1e30f;
#pragma unroll
    for (int i = 0; i < 8; i++) r = fmaxf(r, red[i]);
    return r;
}
__device__ __forceinline__ float gelu_f(float x) {
    float u = 0.7978845608028654f * (x + 0.044715f * x * x * x);
    float t;
    asm("tanh.approx.f32 %0, %1;" : "=f"(t) : "f"(u));
    return 0.5f * x * (1.0f + t);
}
// packed f32x2 FMA (FFMA2): d = a*b + c elementwise on (lo,hi)
__device__ __forceinline__ unsigned long long ffma2(unsigned long long a,
                                                    unsigned long long b,
                                                    unsigned long long c) {
    unsigned long long d;
    asm("fma.rn.f32x2 %0, %1, %2, %3;" : "=l"(d) : "l"(a), "l"(b), "l"(c));
    return d;
}

// ---------------- stage 1: positional encoding + concat ----------------
__global__ void k_pe(const float* __restrict__ x, const float* __restrict__ p) {
    int i = blockIdx.x * blockDim.x + threadIdx.x;
    if (i >= N_NODES * D_IN) return;
    int n = i / D_IN, j = i - n * D_IN;
    float v;
    if (j < F_IN) {
        v = x[n * F_IN + j];
    } else {
        int jj = j - F_IN;
        int d = jj >> 3, f = jj & 7;
        float freq = 3.14159265358979323846f * (float)(1 << f);
        v = sinf(p[n * 3 + d] * freq);
    }
    g_xc[i] = v;
}

// ---------------- stage 2: degree / scatter ----------------
__global__ void k_deg_init() {
    int n = blockIdx.x * blockDim.x + threadIdx.x;
    if (n < N_NODES) g_deg[n] = 1.0f;  // self loop
}
__global__ void k_deg_count(const int* __restrict__ ei) {
    int e = blockIdx.x * blockDim.x + threadIdx.x;
    if (e < E_EDGES) atomicAdd(&g_deg[ei[E_EDGES + e]], 1.0f);
}
__global__ void k_dinv() {
    int n = blockIdx.x * blockDim.x + threadIdx.x;
    if (n < N_NODES) g_deg[n] = rsqrtf(fmaxf(g_deg[n], 1e-12f));
}
__global__ void k_agg_init() {
    int i = blockIdx.x * blockDim.x + threadIdx.x;
    if (i >= N_NODES * D_IN) return;
    int n = i / D_IN;
    float d = g_deg[n];
    g_agg[i] = d * d * g_xc[i];
}
__global__ void k_scatter(const int* __restrict__ ei) {
    int i = blockIdx.x * blockDim.x + threadIdx.x;  // E*64 total
    int e = i >> 6, j = i & 63;
    if (j >= D_IN) return;
    int r = ei[e];
    int c = ei[E_EDGES + e];
    float coef = g_deg[r] * g_deg[c];
    atomicAdd(&g_agg[c * D_IN + j], coef * g_xc[r * D_IN + j]);
}

// ---------------- stage 3: GCN matmul + bias + ln_pre, scatter to dense ----------------
__global__ void __launch_bounds__(256) k_gcn(const float* __restrict__ w,
                                             const float* __restrict__ bias,
                                             const float* __restrict__ lns,
                                             const float* __restrict__ lnb) {
    int n = blockIdx.x;
    int t = threadIdx.x;
    __shared__ float a[D_IN];
    __shared__ float red[8];
    if (t < D_IN) a[t] = g_agg[n * D_IN + t];
    __syncthreads();
    float acc = bias[t];
#pragma unroll
    for (int i = 0; i < D_IN; i++) acc += a[i] * w[i * W + t];
    float s1 = block_sum256(acc, red);
    float s2 = block_sum256(acc * acc, red);
    float m = s1 * (1.0f / W);
    float var = s2 * (1.0f / W) - m * m;
    float o = (acc - m) * rsqrtf(var + 1e-5f) * lns[t] + lnb[t];
    int b = n / NPG, pos = n - b * NPG;
    g_xd[(size_t)(b * S + pos + 1) * W + t] = o;
}
__global__ void __launch_bounds__(256) k_cls(const float* __restrict__ cls,
                                             const float* __restrict__ lns,
                                             const float* __restrict__ lnb) {
    int t = threadIdx.x;
    __shared__ float red[8];
    float v = cls[t];
    float s1 = block_sum256(v, red);
    float s2 = block_sum256(v * v, red);
    float m = s1 * (1.0f / W);
    float var = s2 * (1.0f / W) - m * m;
    float o = (v - m) * rsqrtf(var + 1e-5f) * lns[t] + lnb[t];
    g_xd[(size_t)blockIdx.x * S * W + t] = o;
}

// ---------------- LayerNorm rows: g_xd -> g_h1 ----------------
__global__ void __launch_bounds__(256) k_ln(const float* __restrict__ s,
                                            const float* __restrict__ b) {
    int row = blockIdx.x, t = threadIdx.x;
    __shared__ float red[8];
    float v = g_xd[(size_t)row * W + t];
    float s1 = block_sum256(v, red);
    float s2 = block_sum256(v * v, red);
    float m = s1 * (1.0f / W);
    float var = s2 * (1.0f / W) - m * m;
    g_h1[(size_t)row * W + t] = (v - m) * rsqrtf(var + 1e-5f) * s[t] + b[t];
}

// ---------------- packed-f32x2 GEMM: C = [res +] act(A*B + bias) ----------------
// A[M,K] row-major, B[K,N] row-major. M mult of 128, N mult of 256, K mult of 8.
// 128x256 tile, 256 threads, 8x16 micro-tile per thread via FFMA2.
#define BM 128
#define BN 256
#define BK 8
__global__ void __launch_bounds__(256) k_gemm(const float* __restrict__ A,
                                              const float* __restrict__ Bw,
                                              const float* __restrict__ bias,
                                              const float* __restrict__ Res,
                                              float* __restrict__ C,
                                              int K, int Nn, int act, int has_res) {
    // A stored duplicated: value of row r at columns 2r and 2r+1 -> (a,a) pairs
    __shared__ __align__(16) float As2[2][BK][2 * BM + 8];
    __shared__ __align__(16) float Bs[2][BK][BN + 8];

    int bm = blockIdx.y * BM, bn = blockIdx.x * BN;
    int t = threadIdx.x;
    int tx = t & 15, ty = t >> 4;   // 16 x 16 thread grid

    // global A load: thread -> (row = t/2, k-quad = (t&1)*4)
    int arow = t >> 1, ak = (t & 1) * 4;
    // global B load: 2 float4 per thread; f4 idx = t and t+256
    int brow = t >> 6;              // 0..3 (second load uses brow+4)
    int bcol = (t & 63) * 4;

    const float* Ag = A + (size_t)(bm + arow) * K + ak;
    const float* Bg = Bw + bn + bcol;

    unsigned long long acc[8][8];
#pragma unroll
    for (int i = 0; i < 8; i++)
#pragma unroll
        for (int j = 0; j < 8; j++) acc[i][j] = 0ull;

    float4 av, bv0, bv1;
    av  = *(const float4*)(Ag);
    bv0 = *(const float4*)(Bg + (size_t)brow * Nn);
    bv1 = *(const float4*)(Bg + (size_t)(brow + 4) * Nn);

    // store tile 0
#pragma unroll
    for (int j = 0; j < 4; j++) {
        float v = ((const float*)&av)[j];
        *(float2*)&As2[0][ak + j][2 * arow] = make_float2(v, v);
    }
    *(float4*)&Bs[0][brow][bcol]     = bv0;
    *(float4*)&Bs[0][brow + 4][bcol] = bv1;
    __syncthreads();

    int buf = 0;
    for (int k0 = 0;;) {
        int kn = k0 + BK;
        bool more = kn < K;
        if (more) {
            av  = *(const float4*)(Ag + kn);
            bv0 = *(const float4*)(Bg + (size_t)(kn + brow) * Nn);
            bv1 = *(const float4*)(Bg + (size_t)(kn + brow + 4) * Nn);
        }
#pragma unroll
        for (int kk = 0; kk < BK; kk++) {
            unsigned long long a2[8], b2[8];
            const ulonglong2* ap = (const ulonglong2*)&As2[buf][kk][ty * 16];
            ulonglong2 q0 = ap[0], q1 = ap[1], q2 = ap[2], q3 = ap[3];
            a2[0] = q0.x; a2[1] = q0.y; a2[2] = q1.x; a2[3] = q1.y;
            a2[4] = q2.x; a2[5] = q2.y; a2[6] = q3.x; a2[7] = q3.y;
#pragma unroll
            for (int jj = 0; jj < 8; jj++)
                b2[jj] = *(const unsigned long long*)&Bs[buf][kk][jj * 32 + tx * 2];
#pragma unroll
            for (int i = 0; i < 8; i++)
#pragma unroll
                for (int jj = 0; jj < 8; jj++)
                    acc[i][jj] = ffma2(a2[i], b2[jj], acc[i][jj]);
        }
        if (!more) break;
        int nb = buf ^ 1;
#pragma unroll
        for (int j = 0; j < 4; j++) {
            float v = ((const float*)&av)[j];
            *(float2*)&As2[nb][ak + j][2 * arow] = make_float2(v, v);
        }
        *(float4*)&Bs[nb][brow][bcol]     = bv0;
        *(float4*)&Bs[nb][brow + 4][bcol] = bv1;
        __syncthreads();
        buf = nb;
        k0 = kn;
    }

    // epilogue: thread covers rows bm+ty*8+i, col pairs bn + 32*jj + 2*tx
#pragma unroll
    for (int i = 0; i < 8; i++) {
        int row = bm + ty * 8 + i;
#pragma unroll
        for (int jj = 0; jj < 8; jj++) {
            int col = bn + jj * 32 + tx * 2;
            unsigned long long v = acc[i][jj];
            float lo = __uint_as_float((unsigned)(v & 0xffffffffull));
            float hi = __uint_as_float((unsigned)(v >> 32));
            float2 bb = *(const float2*)&bias[col];
            lo += bb.x; hi += bb.y;
            if (act == 1) { lo = gelu_f(lo); hi = gelu_f(hi); }
            if (has_res) {
                float2 r = *(const float2*)&Res[(size_t)row * Nn + col];
                lo += r.x; hi += r.y;
            }
            *(float2*)&C[(size_t)row * Nn + col] = make_float2(lo, hi);
        }
    }
}

// ---------------- attention (one block per (b,h)) ----------------
__global__ void __launch_bounds__(256) k_attn() {
    extern __shared__ float sm[];
    float* Ks = sm;                  // S*33
    float* Vs = Ks + S * 33;         // S*33
    float* sc = Vs + S * 33;         // S
    float* part = sc + S;            // 256
    __shared__ float qv[DH];
    __shared__ float red[8];

    int bh = blockIdx.x;
    int b = bh >> 3, h = bh & 7;
    int t = threadIdx.x;
    const float* base = g_qkv + (size_t)b * S * (3 * W);

    for (int idx = t; idx < S * DH; idx += 256) {
        int s_ = idx >> 5, d = idx & 31;
        Ks[s_ * 33 + d] = base[(size_t)s_ * 768 + 256 + h * 32 + d];
        Vs[s_ * 33 + d] = base[(size_t)s_ * 768 + 512 + h * 32 + d];
    }
    __syncthreads();

    const float scale = 0.17677669529663687f;  // 1/sqrt(32)
    for (int q = 0; q < S; q++) {
        if (t < DH) qv[t] = base[(size_t)q * 768 + h * 32 + t];
        __syncthreads();
        float lmax = -1e30f;
        for (int k = t; k < S; k += 256) {
            float s = 0.f;
#pragma unroll
            for (int d = 0; d < DH; d++) s += qv[d] * Ks[k * 33 + d];
            s *= scale;
            if (q > 0 && k > q) s = -1e9f;
            sc[k] = s;
            lmax = fmaxf(lmax, s);
        }
        float m = block_max256(lmax, red);
        float lsum = 0.f;
        for (int k = t; k < S; k += 256) {
            float e = __expf(sc[k] - m);
            sc[k] = e;
            lsum += e;
        }
        float ssum = block_sum256(lsum, red);
        float inv = 1.0f / ssum;
        __syncthreads();  // sc[] fully written & visible
        int d = t & 31, g = t >> 5;
        float accv = 0.f;
        for (int k = g; k < S; k += 8) accv += sc[k] * Vs[k * 33 + d];
        part[t] = accv;
        __syncthreads();
        if (t < DH) {
            float o = 0.f;
#pragma unroll
            for (int g2 = 0; g2 < 8; g2++) o += part[g2 * 32 + t];
            g_attn[((size_t)b * S + q) * W + h * 32 + t] = o * inv;
        }
        __syncthreads();
    }
}

// ---------------- decoder (fused, one block per graph) ----------------
__global__ void __launch_bounds__(256) k_dec(const float* __restrict__ lns,
                                             const float* __restrict__ lnb,
                                             const float* __restrict__ w1,
                                             const float* __restrict__ b1,
                                             const float* __restrict__ w2,
                                             const float* __restrict__ b2,
                                             const float* __restrict__ w3,
                                             const float* __restrict__ b3,
                                             float* __restrict__ outp) {
    int b = blockIdx.x, t = threadIdx.x;
    __shared__ float cls[W];
    __shared__ float h1[HID];
    __shared__ float h2[HID];
    __shared__ float red[8];
    float v = g_xd[(size_t)b * S * W + t];
    float s1 = block_sum256(v, red);
    float s2 = block_sum256(v * v, red);
    float m = s1 * (1.0f / W);
    float var = s2 * (1.0f / W) - m * m;
    cls[t] = (v - m) * rsqrtf(var + 1e-5f) * lns[t] + lnb[t];
    __syncthreads();
    for (int j = t; j < HID; j += 256) {
        float a = b1[j];
#pragma unroll 8
        for (int i = 0; i < W; i++) a += cls[i] * w1[i * HID + j];
        h1[j] = fmaxf(a, 0.f);
    }
    __syncthreads();
    for (int j = t; j < HID; j += 256) {
        float a = b2[j];
#pragma unroll 8
        for (int i = 0; i < HID; i++) a += h1[i] * w2[i * HID + j];
        h2[j] = fmaxf(a, 0.f);
    }
    __syncthreads();
    if (t < OUT_D) {
        float a = b3[t];
#pragma unroll 8
        for (int i = 0; i < HID; i++) a += h2[i] * w3[i * OUT_D + t];
        outp[b * OUT_D + t] = fmaxf(a, 0.f);
    }
}

// ---------------- launch ----------------
extern "C" void kernel_launch(void* const* d_in, const int* in_sizes, int n_in,
                              void* d_out, int out_size) {
    const float* x          = (const float*)d_in[0];
    const float* p          = (const float*)d_in[1];
    const int*   edge_index = (const int*)d_in[2];
    // d_in[3] = batch (structure known: arange(N)//NPG) — unused
    const float* gcn_w      = (const float*)d_in[4];
    const float* gcn_b      = (const float*)d_in[5];
    const float* cls_token  = (const float*)d_in[6];
    const float* ln_pre_s   = (const float*)d_in[7];
    const float* ln_pre_b   = (const float*)d_in[8];
    const float* norm1_s    = (const float*)d_in[9];
    const float* norm1_b    = (const float*)d_in[10];
    const float* in_proj_w  = (const float*)d_in[11];
    const float* in_proj_b  = (const float*)d_in[12];
    const float* out_proj_w = (const float*)d_in[13];
    const float* out_proj_b = (const float*)d_in[14];
    const float* norm2_s    = (const float*)d_in[15];
    const float* norm2_b    = (const float*)d_in[16];
    const float* ff_w1      = (const float*)d_in[17];
    const float* ff_b1      = (const float*)d_in[18];
    const float* ff_w2      = (const float*)d_in[19];
    const float* ff_b2      = (const float*)d_in[20];
    const float* ln_post_s  = (const float*)d_in[21];
    const float* ln_post_b  = (const float*)d_in[22];
    const float* dec_w1     = (const float*)d_in[23];
    const float* dec_b1     = (const float*)d_in[24];
    const float* dec_w2     = (const float*)d_in[25];
    const float* dec_b2     = (const float*)d_in[26];
    const float* dec_w3     = (const float*)d_in[27];
    const float* dec_b3     = (const float*)d_in[28];
    float* out = (float*)d_out;

    float *p_h1, *p_qkv, *p_attn, *p_ff, *p_xd;
    cudaGetSymbolAddress((void**)&p_h1, g_h1);
    cudaGetSymbolAddress((void**)&p_qkv, g_qkv);
    cudaGetSymbolAddress((void**)&p_attn, g_attn);
    cudaGetSymbolAddress((void**)&p_ff, g_ff);
    cudaGetSymbolAddress((void**)&p_xd, g_xd);

    const int attn_smem = (2 * S * 33 + S + 256) * 4;
    cudaFuncSetAttribute(k_attn, cudaFuncAttributeMaxDynamicSharedMemorySize, attn_smem);

    // GCN front-end
    k_pe<<<(N_NODES * D_IN + 255) / 256, 256>>>(x, p);
    k_deg_init<<<(N_NODES + 255) / 256, 256>>>();
    k_deg_count<<<E_EDGES / 256, 256>>>(edge_index);
    k_dinv<<<(N_NODES + 255) / 256, 256>>>();
    k_agg_init<<<(N_NODES * D_IN + 255) / 256, 256>>>();
    k_scatter<<<(E_EDGES * 64) / 256, 256>>>(edge_index);
    k_gcn<<<N_NODES, 256>>>(gcn_w, gcn_b, ln_pre_s, ln_pre_b);
    k_cls<<<B_GR, 256>>>(cls_token, ln_pre_s, ln_pre_b);

    // transformer layers
    for (int l = 0; l < LAYERS; l++) {
        k_ln<<<MROWS, 256>>>(norm1_s + l * W, norm1_b + l * W);
        k_gemm<<<dim3(768 / BN, MPAD / BM), 256>>>(p_h1, in_proj_w + (size_t)l * W * 3 * W,
                                                   in_proj_b + l * 3 * W, nullptr, p_qkv,
                                                   W, 3 * W, 0, 0);
        k_attn<<<B_GR * HEADS, 256, attn_smem>>>();
        k_gemm<<<dim3(W / BN, MPAD / BM), 256>>>(p_attn, out_proj_w + (size_t)l * W * W,
                                                 out_proj_b + l * W, p_xd, p_xd,
                                                 W, W, 0, 1);
        k_ln<<<MROWS, 256>>>(norm2_s + l * W, norm2_b + l * W);
        k_gemm<<<dim3(DFF / BN, MPAD / BM), 256>>>(p_h1, ff_w1 + (size_t)l * W * DFF,
                                                   ff_b1 + l * DFF, nullptr, p_ff,
                                                   W, DFF, 1, 0);
        k_gemm<<<dim3(W / BN, MPAD / BM), 256>>>(p_ff, ff_w2 + (size_t)l * DFF * W,
                                                 ff_b2 + l * W, p_xd, p_xd,
                                                 DFF, W, 1, 1);
    }

    // decoder on cls rows
    k_dec<<<B_GR, 256>>>(ln_post_s, ln_post_b, dec_w1, dec_b1, dec_w2, dec_b2,
                         dec_w3, dec_b3, out);
    (void)in_sizes; (void)n_in; (void)out_size;
}

// round 3
// speedup vs baseline: 1.8991x; 1.7834x over previous
#include <cuda_runtime.h>
#include <math.h>

// ---------------- problem constants ----------------
#define N_NODES 16384
#define B_GR    64
#define NPG     256
#define E_EDGES 524288
#define F_IN    32
#define D_IN    56        // 32 + 3*8
#define W       256
#define S       257
#define HEADS   8
#define DH      32
#define DFF     1024
#define HID     512
#define OUT_D   64
#define LAYERS  2
#define MROWS   (B_GR * S)   // 16448
#define MPAD    16512        // 129 * 128

// ---------------- scratch (device globals; no allocs) ----------------
__device__ float g_xc  [N_NODES * D_IN];
__device__ float g_agg [N_NODES * D_IN];
__device__ float g_deg [N_NODES];
__device__ float g_xd  [MPAD * W];
__device__ float g_h1  [MPAD * W];
__device__ float g_qkv [MPAD * 3 * W];
__device__ float g_attn[MPAD * W];
__device__ float g_ff  [MPAD * DFF];

// ---------------- helpers ----------------
__device__ __forceinline__ float warp_sum(float v) {
#pragma unroll
    for (int o = 16; o > 0; o >>= 1) v += __shfl_xor_sync(0xffffffffu, v, o);
    return v;
}
__device__ __forceinline__ float block_sum256(float v, float* red) {
    __syncthreads();
    v = warp_sum(v);
    if ((threadIdx.x & 31) == 0) red[threadIdx.x >> 5] = v;
    __syncthreads();
    float r = 0.f;
#pragma unroll
    for (int i = 0; i < 8; i++) r += red[i];
    return r;
}
__device__ __forceinline__ float gelu_f(float x) {
    float u = 0.7978845608028654f * (x + 0.044715f * x * x * x);
    float t;
    asm("tanh.approx.f32 %0, %1;" : "=f"(t) : "f"(u));
    return 0.5f * x * (1.0f + t);
}
typedef unsigned long long ull;
__device__ __forceinline__ ull ffma2(ull a, ull b, ull c) {
    ull d;
    asm("fma.rn.f32x2 %0, %1, %2, %3;" : "=l"(d) : "l"(a), "l"(b), "l"(c));
    return d;
}
__device__ __forceinline__ ull mul2(ull a, ull b) {
    ull d;
    asm("mul.rn.f32x2 %0, %1, %2;" : "=l"(d) : "l"(a), "l"(b));
    return d;
}
__device__ __forceinline__ ull pack2(float x) {
    ull d;
    asm("mov.b64 %0, {%1, %1};" : "=l"(d) : "f"(x));
    return d;
}
__device__ __forceinline__ float lo2(ull v) { return __uint_as_float((unsigned)(v & 0xffffffffull)); }
__device__ __forceinline__ float hi2(ull v) { return __uint_as_float((unsigned)(v >> 32)); }

// ---------------- stage 1: positional encoding + concat (+ deg init) ----------------
__global__ void k_pe(const float* __restrict__ x, const float* __restrict__ p) {
    int i = blockIdx.x * blockDim.x + threadIdx.x;
    if (i >= N_NODES * D_IN) return;
    if (i < N_NODES) g_deg[i] = 1.0f;  // self loop
    int n = i / D_IN, j = i - n * D_IN;
    float v;
    if (j < F_IN) {
        v = x[n * F_IN + j];
    } else {
        int jj = j - F_IN;
        int d = jj >> 3, f = jj & 7;
        float freq = 3.14159265358979323846f * (float)(1 << f);
        v = sinf(p[n * 3 + d] * freq);
    }
    g_xc[i] = v;
}

// ---------------- stage 2: degree / scatter ----------------
__global__ void k_deg_count(const int* __restrict__ ei) {
    int e = blockIdx.x * blockDim.x + threadIdx.x;
    if (e < E_EDGES) atomicAdd(&g_deg[ei[E_EDGES + e]], 1.0f);
}
__global__ void k_agg_init() {
    int i = blockIdx.x * blockDim.x + threadIdx.x;
    if (i >= N_NODES * D_IN) return;
    int n = i / D_IN;
    float d = rsqrtf(fmaxf(g_deg[n], 1e-12f));
    g_agg[i] = d * d * g_xc[i];
}
__global__ void k_scatter(const int* __restrict__ ei) {
    int i = blockIdx.x * blockDim.x + threadIdx.x;  // E*64 total
    int e = i >> 6, j = i & 63;
    if (j >= D_IN) return;
    int r = ei[e];
    int c = ei[E_EDGES + e];
    float coef = rsqrtf(fmaxf(g_deg[r], 1e-12f)) * rsqrtf(fmaxf(g_deg[c], 1e-12f));
    atomicAdd(&g_agg[c * D_IN + j], coef * g_xc[r * D_IN + j]);
}

// ---------------- stage 3: GCN matvec + bias + ln_pre (+ cls rows) ----------------
__global__ void __launch_bounds__(256) k_gcn(const float* __restrict__ w,
                                             const float* __restrict__ bias,
                                             const float* __restrict__ cls_tok,
                                             const float* __restrict__ lns,
                                             const float* __restrict__ lnb) {
    int blk = blockIdx.x;
    int t = threadIdx.x;
    __shared__ float a[D_IN];
    __shared__ float red[8];
    float acc;
    size_t dst;
    if (blk < N_NODES) {
        int n = blk;
        if (t < D_IN) a[t] = g_agg[n * D_IN + t];
        __syncthreads();
        acc = bias[t];
#pragma unroll
        for (int i = 0; i < D_IN; i++) acc += a[i] * w[i * W + t];
        int b = n / NPG, pos = n - b * NPG;
        dst = (size_t)(b * S + pos + 1) * W + t;
    } else {
        acc = cls_tok[t];
        dst = (size_t)(blk - N_NODES) * S * W + t;
    }
    float s1 = block_sum256(acc, red);
    float s2 = block_sum256(acc * acc, red);
    float m = s1 * (1.0f / W);
    float var = s2 * (1.0f / W) - m * m;
    g_xd[dst] = (acc - m) * rsqrtf(var + 1e-5f) * lns[t] + lnb[t];
}

// ---------------- LayerNorm rows: g_xd -> g_h1 ----------------
__global__ void __launch_bounds__(256) k_ln(const float* __restrict__ s,
                                            const float* __restrict__ b) {
    int row = blockIdx.x, t = threadIdx.x;
    __shared__ float red[8];
    float v = g_xd[(size_t)row * W + t];
    float s1 = block_sum256(v, red);
    float s2 = block_sum256(v * v, red);
    float m = s1 * (1.0f / W);
    float var = s2 * (1.0f / W) - m * m;
    g_h1[(size_t)row * W + t] = (v - m) * rsqrtf(var + 1e-5f) * s[t] + b[t];
}

// ---------------- packed-f32x2 GEMM: C = [res +] act(A*B + bias) ----------------
// A[M,K] rm, B[K,N] rm. 128x128 tile, 128 threads, 8x(8 pair) micro-tile, 2 CTAs/SM.
#define BM 128
#define BN 128
#define BK 8
__global__ void __launch_bounds__(128, 2) k_gemm(const float* __restrict__ A,
                                                 const float* __restrict__ Bw,
                                                 const float* __restrict__ bias,
                                                 const float* __restrict__ Res,
                                                 float* __restrict__ C,
                                                 int K, int Nn, int act, int has_res) {
    // A duplicated pairwise: row r lives at columns 2r, 2r+1
    __shared__ __align__(16) float As2[2][BK][2 * BM + 8];
    __shared__ __align__(16) float Bs[2][BK][BN + 8];

    int bm = blockIdx.y * BM, bn = blockIdx.x * BN;
    int t = threadIdx.x;          // 0..127
    int tx = t & 7, ty = t >> 3;  // 8 x 16 thread grid

    const float* Ag = A + (size_t)(bm + t) * K;   // one row per thread
    int br = t >> 5, bc = (t & 31) * 4;
    const float* Bg = Bw + bn + bc;

    ull acc[8][8];
#pragma unroll
    for (int i = 0; i < 8; i++)
#pragma unroll
        for (int j = 0; j < 8; j++) acc[i][j] = 0ull;

    float4 a0, a1, bv0, bv1;
    a0  = *(const float4*)(Ag);
    a1  = *(const float4*)(Ag + 4);
    bv0 = *(const float4*)(Bg + (size_t)br * Nn);
    bv1 = *(const float4*)(Bg + (size_t)(br + 4) * Nn);

#pragma unroll
    for (int j = 0; j < 4; j++) {
        float v0 = ((const float*)&a0)[j];
        float v1 = ((const float*)&a1)[j];
        *(float2*)&As2[0][j][2 * t]     = make_float2(v0, v0);
        *(float2*)&As2[0][4 + j][2 * t] = make_float2(v1, v1);
    }
    *(float4*)&Bs[0][br][bc]     = bv0;
    *(float4*)&Bs[0][br + 4][bc] = bv1;
    __syncthreads();

    int buf = 0;
    for (int k0 = 0;;) {
        int kn = k0 + BK;
        bool more = kn < K;
        if (more) {
            a0  = *(const float4*)(Ag + kn);
            a1  = *(const float4*)(Ag + kn + 4);
            bv0 = *(const float4*)(Bg + (size_t)(kn + br) * Nn);
            bv1 = *(const float4*)(Bg + (size_t)(kn + br + 4) * Nn);
        }
#pragma unroll
        for (int kk = 0; kk < BK; kk++) {
            ull a2[8], b2[8];
            const ulonglong2* ap = (const ulonglong2*)&As2[buf][kk][ty * 16];
            ulonglong2 q0 = ap[0], q1 = ap[1], q2 = ap[2], q3 = ap[3];
            a2[0] = q0.x; a2[1] = q0.y; a2[2] = q1.x; a2[3] = q1.y;
            a2[4] = q2.x; a2[5] = q2.y; a2[6] = q3.x; a2[7] = q3.y;
#pragma unroll
            for (int jj = 0; jj < 8; jj++)
                b2[jj] = *(const ull*)&Bs[buf][kk][jj * 16 + tx * 2];
#pragma unroll
            for (int i = 0; i < 8; i++)
#pragma unroll
                for (int jj = 0; jj < 8; jj++)
                    acc[i][jj] = ffma2(a2[i], b2[jj], acc[i][jj]);
        }
        if (!more) break;
        int nb = buf ^ 1;
#pragma unroll
        for (int j = 0; j < 4; j++) {
            float v0 = ((const float*)&a0)[j];
            float v1 = ((const float*)&a1)[j];
            *(float2*)&As2[nb][j][2 * t]     = make_float2(v0, v0);
            *(float2*)&As2[nb][4 + j][2 * t] = make_float2(v1, v1);
        }
        *(float4*)&Bs[nb][br][bc]     = bv0;
        *(float4*)&Bs[nb][br + 4][bc] = bv1;
        __syncthreads();
        buf = nb;
        k0 = kn;
    }

#pragma unroll
    for (int i = 0; i < 8; i++) {
        int row = bm + ty * 8 + i;
#pragma unroll
        for (int jj = 0; jj < 8; jj++) {
            int col = bn + jj * 16 + tx * 2;
            float lo = lo2(acc[i][jj]);
            float hi = hi2(acc[i][jj]);
            float2 bb = *(const float2*)&bias[col];
            lo += bb.x; hi += bb.y;
            if (act == 1) { lo = gelu_f(lo); hi = gelu_f(hi); }
            if (has_res) {
                float2 r = *(const float2*)&Res[(size_t)row * Nn + col];
                lo += r.x; hi += r.y;
            }
            *(float2*)&C[(size_t)row * Nn + col] = make_float2(lo, hi);
        }
    }
}

// ---------------- attention: one thread = one query row, flash-style ----------------
// block = (b,h), 288 threads (t<=256 active), K/V staged in dyn smem.
__global__ void __launch_bounds__(288) k_attn() {
    extern __shared__ float sm[];
    float* Ks = sm;            // S*32
    float* Vs = sm + S * DH;   // S*32

    int bh = blockIdx.x;
    int b = bh >> 3, h = bh & 7;
    int t = threadIdx.x;
    const float* base = g_qkv + (size_t)b * S * 768;

    for (int idx = t; idx < S * 8; idx += 288) {
        int s_ = idx >> 3, d4 = idx & 7;
        const float* src = base + (size_t)s_ * 768 + h * 32 + d4 * 4;
        ((float4*)Ks)[idx] = *(const float4*)(src + 256);
        ((float4*)Vs)[idx] = *(const float4*)(src + 512);
    }
    __syncthreads();
    if (t > 256) return;

    int q = t;
    ull qv[16];
    {
        const ull* qp = (const ull*)(base + (size_t)q * 768 + h * 32);
#pragma unroll
        for (int i = 0; i < 16; i++) qv[i] = qp[i];
    }
    ull o[16];
#pragma unroll
    for (int i = 0; i < 16; i++) o[i] = 0ull;
    float m = -1e30f, l = 0.f;
    const float scale = 0.17677669529663687f;  // 1/sqrt(32)
    int kmax = (q == 0) ? 256 : q;

    for (int k = 0; k <= kmax; k++) {
        const ull* kr = (const ull*)&Ks[k * DH];
        ull sacc = 0ull;
#pragma unroll
        for (int i = 0; i < 16; i++) sacc = ffma2(qv[i], kr[i], sacc);
        float s = (lo2(sacc) + hi2(sacc)) * scale;
        float mn = fmaxf(m, s);
        float c = __expf(m - mn);
        float e = __expf(s - mn);
        l = l * c + e;
        ull c2 = pack2(c), e2 = pack2(e);
        const ull* vr = (const ull*)&Vs[k * DH];
#pragma unroll
        for (int i = 0; i < 16; i++) o[i] = ffma2(e2, vr[i], mul2(o[i], c2));
        m = mn;
    }
    float inv = 1.0f / l;
    float* op = g_attn + ((size_t)b * S + q) * W + h * 32;
#pragma unroll
    for (int i = 0; i < 16; i++) {
        float2 v = make_float2(lo2(o[i]) * inv, hi2(o[i]) * inv);
        *(float2*)&op[i * 2] = v;
    }
}

// ---------------- decoder (fused, one block per graph) ----------------
__global__ void __launch_bounds__(256) k_dec(const float* __restrict__ lns,
                                             const float* __restrict__ lnb,
                                             const float* __restrict__ w1,
                                             const float* __restrict__ b1,
                                             const float* __restrict__ w2,
                                             const float* __restrict__ b2,
                                             const float* __restrict__ w3,
                                             const float* __restrict__ b3,
                                             float* __restrict__ outp) {
    int b = blockIdx.x, t = threadIdx.x;
    __shared__ float cls[W];
    __shared__ float h1[HID];
    __shared__ float h2[HID];
    __shared__ float red[8];
    float v = g_xd[(size_t)b * S * W + t];
    float s1 = block_sum256(v, red);
    float s2 = block_sum256(v * v, red);
    float m = s1 * (1.0f / W);
    float var = s2 * (1.0f / W) - m * m;
    cls[t] = (v - m) * rsqrtf(var + 1e-5f) * lns[t] + lnb[t];
    __syncthreads();
    for (int j = t; j < HID; j += 256) {
        float a = b1[j];
#pragma unroll 8
        for (int i = 0; i < W; i++) a += cls[i] * w1[i * HID + j];
        h1[j] = fmaxf(a, 0.f);
    }
    __syncthreads();
    for (int j = t; j < HID; j += 256) {
        float a = b2[j];
#pragma unroll 8
        for (int i = 0; i < HID; i++) a += h1[i] * w2[i * HID + j];
        h2[j] = fmaxf(a, 0.f);
    }
    __syncthreads();
    if (t < OUT_D) {
        float a = b3[t];
#pragma unroll 8
        for (int i = 0; i < HID; i++) a += h2[i] * w3[i * OUT_D + t];
        outp[b * OUT_D + t] = fmaxf(a, 0.f);
    }
}

// ---------------- launch ----------------
extern "C" void kernel_launch(void* const* d_in, const int* in_sizes, int n_in,
                              void* d_out, int out_size) {
    const float* x          = (const float*)d_in[0];
    const float* p          = (const float*)d_in[1];
    const int*   edge_index = (const int*)d_in[2];
    // d_in[3] = batch (structure known: arange(N)//NPG) — unused
    const float* gcn_w      = (const float*)d_in[4];
    const float* gcn_b      = (const float*)d_in[5];
    const float* cls_token  = (const float*)d_in[6];
    const float* ln_pre_s   = (const float*)d_in[7];
    const float* ln_pre_b   = (const float*)d_in[8];
    const float* norm1_s    = (const float*)d_in[9];
    const float* norm1_b    = (const float*)d_in[10];
    const float* in_proj_w  = (const float*)d_in[11];
    const float* in_proj_b  = (const float*)d_in[12];
    const float* out_proj_w = (const float*)d_in[13];
    const float* out_proj_b = (const float*)d_in[14];
    const float* norm2_s    = (const float*)d_in[15];
    const float* norm2_b    = (const float*)d_in[16];
    const float* ff_w1      = (const float*)d_in[17];
    const float* ff_b1      = (const float*)d_in[18];
    const float* ff_w2      = (const float*)d_in[19];
    const float* ff_b2      = (const float*)d_in[20];
    const float* ln_post_s  = (const float*)d_in[21];
    const float* ln_post_b  = (const float*)d_in[22];
    const float* dec_w1     = (const float*)d_in[23];
    const float* dec_b1     = (const float*)d_in[24];
    const float* dec_w2     = (const float*)d_in[25];
    const float* dec_b2     = (const float*)d_in[26];
    const float* dec_w3     = (const float*)d_in[27];
    const float* dec_b3     = (const float*)d_in[28];
    float* out = (float*)d_out;

    float *p_h1, *p_qkv, *p_attn, *p_ff, *p_xd;
    cudaGetSymbolAddress((void**)&p_h1, g_h1);
    cudaGetSymbolAddress((void**)&p_qkv, g_qkv);
    cudaGetSymbolAddress((void**)&p_attn, g_attn);
    cudaGetSymbolAddress((void**)&p_ff, g_ff);
    cudaGetSymbolAddress((void**)&p_xd, g_xd);

    const int attn_smem = 2 * S * DH * 4;  // 65792
    cudaFuncSetAttribute(k_attn, cudaFuncAttributeMaxDynamicSharedMemorySize, attn_smem);

    // GCN front-end
    k_pe<<<(N_NODES * D_IN + 255) / 256, 256>>>(x, p);
    k_deg_count<<<E_EDGES / 256, 256>>>(edge_index);
    k_agg_init<<<(N_NODES * D_IN + 255) / 256, 256>>>();
    k_scatter<<<(E_EDGES * 64) / 256, 256>>>(edge_index);
    k_gcn<<<N_NODES + B_GR, 256>>>(gcn_w, gcn_b, cls_token, ln_pre_s, ln_pre_b);

    // transformer layers
    for (int l = 0; l < LAYERS; l++) {
        k_ln<<<MROWS, 256>>>(norm1_s + l * W, norm1_b + l * W);
        k_gemm<<<dim3(768 / BN, MPAD / BM), 128>>>(p_h1, in_proj_w + (size_t)l * W * 3 * W,
                                                   in_proj_b + l * 3 * W, nullptr, p_qkv,
                                                   W, 3 * W, 0, 0);
        k_attn<<<B_GR * HEADS, 288, attn_smem>>>();
        k_gemm<<<dim3(W / BN, MPAD / BM), 128>>>(p_attn, out_proj_w + (size_t)l * W * W,
                                                 out_proj_b + l * W, p_xd, p_xd,
                                                 W, W, 0, 1);
        k_ln<<<MROWS, 256>>>(norm2_s + l * W, norm2_b + l * W);
        k_gemm<<<dim3(DFF / BN, MPAD / BM), 128>>>(p_h1, ff_w1 + (size_t)l * W * DFF,
                                                   ff_b1 + l * DFF, nullptr, p_ff,
                                                   W, DFF, 1, 0);
        k_gemm<<<dim3(W / BN, MPAD / BM), 128>>>(p_ff, ff_w2 + (size_t)l * DFF * W,
                                                 ff_b2 + l * W, p_xd, p_xd,
                                                 DFF, W, 1, 1);
    }

    // decoder on cls rows
    k_dec<<<B_GR, 256>>>(ln_post_s, ln_post_b, dec_w1, dec_b1, dec_w2, dec_b2,
                         dec_w3, dec_b3, out);
    (void)in_sizes; (void)n_in; (void)out_size;
}

// round 5
// speedup vs baseline: 3.2557x; 1.7143x over previous
#include <cuda_runtime.h>
#include <math.h>
#include <stdint.h>

// ---------------- problem constants ----------------
#define N_NODES 16384
#define B_GR    64
#define NPG     256
#define E_EDGES 524288
#define F_IN    32
#define D_IN    56        // 32 + 3*8
#define W       256
#define S       257
#define HEADS   8
#define DH      32
#define DFF     1024
#define HID     512
#define OUT_D   64
#define LAYERS  2
#define MROWS   (B_GR * S)   // 16448
#define MPAD    16512        // 129 * 128

// ---------------- scratch (device globals; no allocs) ----------------
__device__ float g_xc  [N_NODES * D_IN];
__device__ float g_agg [N_NODES * D_IN];
__device__ float g_deg [N_NODES];
__device__ float g_xd  [MPAD * W];
__device__ float g_h1  [MPAD * W];
__device__ float g_qkv [MPAD * 3 * W];
__device__ float g_attn[MPAD * W];
__device__ float g_ff  [MPAD * DFF];
// transposed weights: per layer: qkvT(768*256) outT(256*256) ff1T(1024*256) ff2T(256*1024)
#define WT_LAYER 786432
#define WT_QKV   0
#define WT_OUT   196608
#define WT_FF1   262144
#define WT_FF2   524288
__device__ float g_wt [2 * WT_LAYER];

// ---------------- helpers ----------------
__device__ __forceinline__ float warp_sum(float v) {
#pragma unroll
    for (int o = 16; o > 0; o >>= 1) v += __shfl_xor_sync(0xffffffffu, v, o);
    return v;
}
__device__ __forceinline__ float block_sum256(float v, float* red) {
    __syncthreads();
    v = warp_sum(v);
    if ((threadIdx.x & 31) == 0) red[threadIdx.x >> 5] = v;
    __syncthreads();
    float r = 0.f;
#pragma unroll
    for (int i = 0; i < 8; i++) r += red[i];
    return r;
}
__device__ __forceinline__ float gelu_f(float x) {
    float u = 0.7978845608028654f * (x + 0.044715f * x * x * x);
    float t;
    asm("tanh.approx.f32 %0, %1;" : "=f"(t) : "f"(u));
    return 0.5f * x * (1.0f + t);
}
typedef unsigned long long ull;
__device__ __forceinline__ ull ffma2(ull a, ull b, ull c) {
    ull d;
    asm("fma.rn.f32x2 %0, %1, %2, %3;" : "=l"(d) : "l"(a), "l"(b), "l"(c));
    return d;
}
__device__ __forceinline__ ull mul2(ull a, ull b) {
    ull d;
    asm("mul.rn.f32x2 %0, %1, %2;" : "=l"(d) : "l"(a), "l"(b));
    return d;
}
__device__ __forceinline__ ull pack2(float x) {
    ull d;
    asm("mov.b64 %0, {%1, %1};" : "=l"(d) : "f"(x));
    return d;
}
__device__ __forceinline__ float lo2(ull v) { return __uint_as_float((unsigned)(v & 0xffffffffull)); }
__device__ __forceinline__ float hi2(ull v) { return __uint_as_float((unsigned)(v >> 32)); }

__device__ __forceinline__ uint32_t s2u(const void* p) {
    uint32_t a;
    asm("{ .reg .u64 t; cvta.to.shared.u64 t, %1; cvt.u32.u64 %0, t; }" : "=r"(a) : "l"(p));
    return a;
}
__device__ __forceinline__ void cp16(uint32_t dst, const void* src) {
    asm volatile("cp.async.cg.shared.global [%0], [%1], 16;" :: "r"(dst), "l"(src));
}
__device__ __forceinline__ void cp_commit() { asm volatile("cp.async.commit_group;" ::: "memory"); }
__device__ __forceinline__ void cp_wait1()  { asm volatile("cp.async.wait_group 1;" ::: "memory"); }

__device__ __forceinline__ uint32_t f2tf(float f) {
    uint32_t r;
    asm("cvt.rna.tf32.f32 %0, %1;" : "=r"(r) : "f"(f));
    return r;
}
__device__ __forceinline__ void mma_tf32(float* d, const uint32_t* a, const uint32_t* b) {
    asm volatile(
        "mma.sync.aligned.m16n8k8.row.col.f32.tf32.tf32.f32 "
        "{%0,%1,%2,%3}, {%4,%5,%6,%7}, {%8,%9}, {%0,%1,%2,%3};"
        : "+f"(d[0]), "+f"(d[1]), "+f"(d[2]), "+f"(d[3])
        : "r"(a[0]), "r"(a[1]), "r"(a[2]), "r"(a[3]), "r"(b[0]), "r"(b[1]));
}

// ---------------- stage 1: positional encoding + concat (+ deg init) ----------------
__global__ void k_pe(const float* __restrict__ x, const float* __restrict__ p) {
    int i = blockIdx.x * blockDim.x + threadIdx.x;
    if (i >= N_NODES * D_IN) return;
    if (i < N_NODES) g_deg[i] = 1.0f;  // self loop
    int n = i / D_IN, j = i - n * D_IN;
    float v;
    if (j < F_IN) {
        v = x[n * F_IN + j];
    } else {
        int jj = j - F_IN;
        int d = jj >> 3, f = jj & 7;
        float freq = 3.14159265358979323846f * (float)(1 << f);
        v = sinf(p[n * 3 + d] * freq);
    }
    g_xc[i] = v;
}

// ---------------- stage 2: degree / scatter ----------------
__global__ void k_deg_count(const int* __restrict__ ei) {
    int e = blockIdx.x * blockDim.x + threadIdx.x;
    if (e < E_EDGES) atomicAdd(&g_deg[ei[E_EDGES + e]], 1.0f);
}
__global__ void k_agg_init() {
    int i = blockIdx.x * blockDim.x + threadIdx.x;
    if (i >= N_NODES * D_IN) return;
    int n = i / D_IN;
    float d = rsqrtf(fmaxf(g_deg[n], 1e-12f));
    g_agg[i] = d * d * g_xc[i];
}
__global__ void k_scatter(const int* __restrict__ ei) {
    int i = blockIdx.x * blockDim.x + threadIdx.x;  // E*64 total
    int e = i >> 6, j = i & 63;
    if (j >= D_IN) return;
    int r = ei[e];
    int c = ei[E_EDGES + e];
    float coef = rsqrtf(fmaxf(g_deg[r], 1e-12f)) * rsqrtf(fmaxf(g_deg[c], 1e-12f));
    atomicAdd(&g_agg[c * D_IN + j], coef * g_xc[r * D_IN + j]);
}

// ---------------- stage 3: GCN matvec + bias + ln_pre (+ cls rows) ----------------
__global__ void __launch_bounds__(256) k_gcn(const float* __restrict__ w,
                                             const float* __restrict__ bias,
                                             const float* __restrict__ cls_tok,
                                             const float* __restrict__ lns,
                                             const float* __restrict__ lnb) {
    int blk = blockIdx.x;
    int t = threadIdx.x;
    __shared__ float a[D_IN];
    __shared__ float red[8];
    float acc;
    size_t dst;
    if (blk < N_NODES) {
        int n = blk;
        if (t < D_IN) a[t] = g_agg[n * D_IN + t];
        __syncthreads();
        acc = bias[t];
#pragma unroll
        for (int i = 0; i < D_IN; i++) acc += a[i] * w[i * W + t];
        int b = n / NPG, pos = n - b * NPG;
        dst = (size_t)(b * S + pos + 1) * W + t;
    } else {
        acc = cls_tok[t];
        dst = (size_t)(blk - N_NODES) * S * W + t;
    }
    float s1 = block_sum256(acc, red);
    float s2 = block_sum256(acc * acc, red);
    float m = s1 * (1.0f / W);
    float var = s2 * (1.0f / W) - m * m;
    g_xd[dst] = (acc - m) * rsqrtf(var + 1e-5f) * lns[t] + lnb[t];
}

// ---------------- LayerNorm rows: g_xd -> g_h1 ----------------
__global__ void __launch_bounds__(256) k_ln(const float* __restrict__ s,
                                            const float* __restrict__ b) {
    int row = blockIdx.x, t = threadIdx.x;
    __shared__ float red[8];
    float v = g_xd[(size_t)row * W + t];
    float s1 = block_sum256(v, red);
    float s2 = block_sum256(v * v, red);
    float m = s1 * (1.0f / W);
    float var = s2 * (1.0f / W) - m * m;
    g_h1[(size_t)row * W + t] = (v - m) * rsqrtf(var + 1e-5f) * s[t] + b[t];
}

// ---------------- weight transpose: dst[N,K] = src[K,N]^T ----------------
__global__ void __launch_bounds__(256) k_tr(const float* __restrict__ src,
                                            float* __restrict__ dst, int K, int N) {
    __shared__ float tile[32][33];
    int bx = blockIdx.x * 32, by = blockIdx.y * 32;
    int tx = threadIdx.x & 31, ty = threadIdx.x >> 5;  // 32x8
#pragma unroll
    for (int j = 0; j < 32; j += 8)
        tile[ty + j][tx] = src[(size_t)(by + ty + j) * N + bx + tx];
    __syncthreads();
#pragma unroll
    for (int j = 0; j < 32; j += 8)
        dst[(size_t)(bx + ty + j) * K + by + tx] = tile[tx][ty + j];
}

// ---------------- tf32 mma.sync GEMM ----------------
// C[M,N] = [Res +] act(A[M,K] * Bt[N,K]^T + bias). Tiles 128x128, Kc=32,
// 256 threads = 8 warps (4m x 2n), warp tile 32x64 = 2x8 mma(m16n8k8).
// dyn smem floats: As[2][128][36] at 0, Bs[2][128][36] at 9216. 73728 bytes.
#define KC 32
#define SROW 36
__device__ __forceinline__ void mmg_load(uint32_t smb, const float* A, const float* Bt,
                                         int bm, int bn, int K, int s, int b, int t) {
    int k0 = s * KC;
    const float* Ag = A + (size_t)bm * K + k0;
    const float* Bg = Bt + (size_t)bn * K + k0;
    uint32_t abase = smb + (uint32_t)(b * 4608) * 4;
    uint32_t bbase = smb + (uint32_t)(9216 + b * 4608) * 4;
#pragma unroll
    for (int i = 0; i < 4; i++) {
        int q = t + i * 256;          // 0..1023
        int row = q >> 3, kq = (q & 7) * 4;
        uint32_t off = (uint32_t)(row * SROW + kq) * 4;
        size_t g = (size_t)row * K + kq;
        cp16(abase + off, Ag + g);
        cp16(bbase + off, Bg + g);
    }
}

__global__ void __launch_bounds__(256, 2) k_gemm_mma(const float* __restrict__ A,
                                                     const float* __restrict__ Bt,
                                                     const float* __restrict__ bias,
                                                     const float* __restrict__ Res,
                                                     float* __restrict__ C,
                                                     int K, int Nn, int act, int has_res) {
    extern __shared__ __align__(16) float smf[];
    uint32_t smb = s2u(smf);
    int bm = blockIdx.y * 128, bn = blockIdx.x * 128;
    int t = threadIdx.x;
    int wid = t >> 5, lane = t & 31;
    int g = lane >> 2, tig = lane & 3;
    int wm = wid & 3, wn = wid >> 2;          // 4 x 2 warp grid

    float acc[2][8][4];
#pragma unroll
    for (int mt = 0; mt < 2; mt++)
#pragma unroll
        for (int nt = 0; nt < 8; nt++)
#pragma unroll
            for (int i = 0; i < 4; i++) acc[mt][nt][i] = 0.f;

    const int T = K / KC;
    mmg_load(smb, A, Bt, bm, bn, K, 0, 0, t);
    cp_commit();
    mmg_load(smb, A, Bt, bm, bn, K, 1, 1, t);
    cp_commit();

    for (int s = 0; s < T; s++) {
        int b = s & 1;
        cp_wait1();
        __syncthreads();
        const float* sA = smf + b * 4608;
        const float* sB = smf + 9216 + b * 4608;
#pragma unroll
        for (int kk = 0; kk < 4; kk++) {
            int k8 = kk * 8;
            uint32_t afr[2][4];
#pragma unroll
            for (int mt = 0; mt < 2; mt++) {
                int m0 = wm * 32 + mt * 16 + g;
                const float* ap = sA + m0 * SROW + k8 + tig;
                afr[mt][0] = f2tf(ap[0]);
                afr[mt][1] = f2tf(ap[8 * SROW]);
                afr[mt][2] = f2tf(ap[4]);
                afr[mt][3] = f2tf(ap[8 * SROW + 4]);
            }
            uint32_t bfr[8][2];
#pragma unroll
            for (int nt = 0; nt < 8; nt++) {
                int n0 = wn * 64 + nt * 8 + g;
                const float* bp = sB + n0 * SROW + k8 + tig;
                bfr[nt][0] = f2tf(bp[0]);
                bfr[nt][1] = f2tf(bp[4]);
            }
#pragma unroll
            for (int mt = 0; mt < 2; mt++)
#pragma unroll
                for (int nt = 0; nt < 8; nt++)
                    mma_tf32(acc[mt][nt], afr[mt], bfr[nt]);
        }
        __syncthreads();
        if (s + 2 < T) mmg_load(smb, A, Bt, bm, bn, K, s + 2, b, t);
        cp_commit();
    }

    // epilogue
#pragma unroll
    for (int mt = 0; mt < 2; mt++) {
        int row0 = bm + wm * 32 + mt * 16 + g;
#pragma unroll
        for (int nt = 0; nt < 8; nt++) {
            int col = bn + wn * 64 + nt * 8 + 2 * tig;
            float2 bb = *(const float2*)&bias[col];
#pragma unroll
            for (int h = 0; h < 2; h++) {
                int row = row0 + h * 8;
                float v0 = acc[mt][nt][2 * h + 0] + bb.x;
                float v1 = acc[mt][nt][2 * h + 1] + bb.y;
                if (act == 1) { v0 = gelu_f(v0); v1 = gelu_f(v1); }
                if (has_res) {
                    float2 r = *(const float2*)&Res[(size_t)row * Nn + col];
                    v0 += r.x; v1 += r.y;
                }
                *(float2*)&C[(size_t)row * Nn + col] = make_float2(v0, v1);
            }
        }
    }
}

// ---------------- attention: one thread = one query row, flash-style ----------------
__global__ void __launch_bounds__(288) k_attn() {
    extern __shared__ float sm[];
    float* Ks = sm;            // S*32
    float* Vs = sm + S * DH;   // S*32

    int bh = blockIdx.x;
    int b = bh >> 3, h = bh & 7;
    int t = threadIdx.x;
    const float* base = g_qkv + (size_t)b * S * 768;

    for (int idx = t; idx < S * 8; idx += 288) {
        int s_ = idx >> 3, d4 = idx & 7;
        const float* src = base + (size_t)s_ * 768 + h * 32 + d4 * 4;
        ((float4*)Ks)[idx] = *(const float4*)(src + 256);
        ((float4*)Vs)[idx] = *(const float4*)(src + 512);
    }
    __syncthreads();
    if (t > 256) return;

    int q = t;
    ull qv[16];
    {
        const ull* qp = (const ull*)(base + (size_t)q * 768 + h * 32);
#pragma unroll
        for (int i = 0; i < 16; i++) qv[i] = qp[i];
    }
    ull o[16];
#pragma unroll
    for (int i = 0; i < 16; i++) o[i] = 0ull;
    float m = -1e30f, l = 0.f;
    const float scale = 0.17677669529663687f;  // 1/sqrt(32)
    int kmax = (q == 0) ? 256 : q;

    for (int k = 0; k <= kmax; k++) {
        const ull* kr = (const ull*)&Ks[k * DH];
        ull sacc = 0ull;
#pragma unroll
        for (int i = 0; i < 16; i++) sacc = ffma2(qv[i], kr[i], sacc);
        float s = (lo2(sacc) + hi2(sacc)) * scale;
        float mn = fmaxf(m, s);
        float c = __expf(m - mn);
        float e = __expf(s - mn);
        l = l * c + e;
        ull c2 = pack2(c), e2 = pack2(e);
        const ull* vr = (const ull*)&Vs[k * DH];
#pragma unroll
        for (int i = 0; i < 16; i++) o[i] = ffma2(e2, vr[i], mul2(o[i], c2));
        m = mn;
    }
    float inv = 1.0f / l;
    float* op = g_attn + ((size_t)b * S + q) * W + h * 32;
#pragma unroll
    for (int i = 0; i < 16; i++) {
        float2 v = make_float2(lo2(o[i]) * inv, hi2(o[i]) * inv);
        *(float2*)&op[i * 2] = v;
    }
}

// ---------------- decoder (fused, one block per graph) ----------------
__global__ void __launch_bounds__(256) k_dec(const float* __restrict__ lns,
                                             const float* __restrict__ lnb,
                                             const float* __restrict__ w1,
                                             const float* __restrict__ b1,
                                             const float* __restrict__ w2,
                                             const float* __restrict__ b2,
                                             const float* __restrict__ w3,
                                             const float* __restrict__ b3,
                                             float* __restrict__ outp) {
    int b = blockIdx.x, t = threadIdx.x;
    __shared__ float cls[W];
    __shared__ float h1[HID];
    __shared__ float h2[HID];
    __shared__ float red[8];
    float v = g_xd[(size_t)b * S * W + t];
    float s1 = block_sum256(v, red);
    float s2 = block_sum256(v * v, red);
    float m = s1 * (1.0f / W);
    float var = s2 * (1.0f / W) - m * m;
    cls[t] = (v - m) * rsqrtf(var + 1e-5f) * lns[t] + lnb[t];
    __syncthreads();
    for (int j = t; j < HID; j += 256) {
        float a = b1[j];
#pragma unroll 8
        for (int i = 0; i < W; i++) a += cls[i] * w1[i * HID + j];
        h1[j] = fmaxf(a, 0.f);
    }
    __syncthreads();
    for (int j = t; j < HID; j += 256) {
        float a = b2[j];
#pragma unroll 8
        for (int i = 0; i < HID; i++) a += h1[i] * w2[i * HID + j];
        h2[j] = fmaxf(a, 0.f);
    }
    __syncthreads();
    if (t < OUT_D) {
        float a = b3[t];
#pragma unroll 8
        for (int i = 0; i < HID; i++) a += h2[i] * w3[i * OUT_D + t];
        outp[b * OUT_D + t] = fmaxf(a, 0.f);
    }
}

// ---------------- launch ----------------
extern "C" void kernel_launch(void* const* d_in, const int* in_sizes, int n_in,
                              void* d_out, int out_size) {
    const float* x          = (const float*)d_in[0];
    const float* p          = (const float*)d_in[1];
    const int*   edge_index = (const int*)d_in[2];
    // d_in[3] = batch (structure known: arange(N)//NPG) — unused
    const float* gcn_w      = (const float*)d_in[4];
    const float* gcn_b      = (const float*)d_in[5];
    const float* cls_token  = (const float*)d_in[6];
    const float* ln_pre_s   = (const float*)d_in[7];
    const float* ln_pre_b   = (const float*)d_in[8];
    const float* norm1_s    = (const float*)d_in[9];
    const float* norm1_b    = (const float*)d_in[10];
    const float* in_proj_w  = (const float*)d_in[11];
    const float* in_proj_b  = (const float*)d_in[12];
    const float* out_proj_w = (const float*)d_in[13];
    const float* out_proj_b = (const float*)d_in[14];
    const float* norm2_s    = (const float*)d_in[15];
    const float* norm2_b    = (const float*)d_in[16];
    const float* ff_w1      = (const float*)d_in[17];
    const float* ff_b1      = (const float*)d_in[18];
    const float* ff_w2      = (const float*)d_in[19];
    const float* ff_b2      = (const float*)d_in[20];
    const float* ln_post_s  = (const float*)d_in[21];
    const float* ln_post_b  = (const float*)d_in[22];
    const float* dec_w1     = (const float*)d_in[23];
    const float* dec_b1     = (const float*)d_in[24];
    const float* dec_w2     = (const float*)d_in[25];
    const float* dec_b2     = (const float*)d_in[26];
    const float* dec_w3     = (const float*)d_in[27];
    const float* dec_b3     = (const float*)d_in[28];
    float* out = (float*)d_out;

    float *p_h1, *p_qkv, *p_attn, *p_ff, *p_xd, *p_wt;
    cudaGetSymbolAddress((void**)&p_h1, g_h1);
    cudaGetSymbolAddress((void**)&p_qkv, g_qkv);
    cudaGetSymbolAddress((void**)&p_attn, g_attn);
    cudaGetSymbolAddress((void**)&p_ff, g_ff);
    cudaGetSymbolAddress((void**)&p_xd, g_xd);
    cudaGetSymbolAddress((void**)&p_wt, g_wt);

    const int attn_smem = 2 * S * DH * 4;  // 65792
    cudaFuncSetAttribute(k_attn, cudaFuncAttributeMaxDynamicSharedMemorySize, attn_smem);
    const int mma_smem = 73728;
    cudaFuncSetAttribute(k_gemm_mma, cudaFuncAttributeMaxDynamicSharedMemorySize, mma_smem);

    // weight transposes (independent of data pipeline)
    for (int l = 0; l < LAYERS; l++) {
        float* wl = p_wt + (size_t)l * WT_LAYER;
        k_tr<<<dim3(768 / 32, 256 / 32), 256>>>(in_proj_w + (size_t)l * W * 768, wl + WT_QKV, 256, 768);
        k_tr<<<dim3(256 / 32, 256 / 32), 256>>>(out_proj_w + (size_t)l * W * W, wl + WT_OUT, 256, 256);
        k_tr<<<dim3(1024 / 32, 256 / 32), 256>>>(ff_w1 + (size_t)l * W * DFF, wl + WT_FF1, 256, 1024);
        k_tr<<<dim3(256 / 32, 1024 / 32), 256>>>(ff_w2 + (size_t)l * DFF * W, wl + WT_FF2, 1024, 256);
    }

    // GCN front-end
    k_pe<<<(N_NODES * D_IN + 255) / 256, 256>>>(x, p);
    k_deg_count<<<E_EDGES / 256, 256>>>(edge_index);
    k_agg_init<<<(N_NODES * D_IN + 255) / 256, 256>>>();
    k_scatter<<<(E_EDGES * 64) / 256, 256>>>(edge_index);
    k_gcn<<<N_NODES + B_GR, 256>>>(gcn_w, gcn_b, cls_token, ln_pre_s, ln_pre_b);

    // transformer layers
    for (int l = 0; l < LAYERS; l++) {
        float* wl = p_wt + (size_t)l * WT_LAYER;
        k_ln<<<MROWS, 256>>>(norm1_s + l * W, norm1_b + l * W);
        k_gemm_mma<<<dim3(6, MPAD / 128), 256, mma_smem>>>(p_h1, wl + WT_QKV,
                                                           in_proj_b + l * 3 * W, nullptr, p_qkv,
                                                           256, 768, 0, 0);
        k_attn<<<B_GR * HEADS, 288, attn_smem>>>();
        k_gemm_mma<<<dim3(2, MPAD / 128), 256, mma_smem>>>(p_attn, wl + WT_OUT,
                                                           out_proj_b + l * W, p_xd, p_xd,
                                                           256, 256, 0, 1);
        k_ln<<<MROWS, 256>>>(norm2_s + l * W, norm2_b + l * W);
        k_gemm_mma<<<dim3(8, MPAD / 128), 256, mma_smem>>>(p_h1, wl + WT_FF1,
                                                           ff_b1 + l * DFF, nullptr, p_ff,
                                                           256, 1024, 1, 0);
        k_gemm_mma<<<dim3(2, MPAD / 128), 256, mma_smem>>>(p_ff, wl + WT_FF2,
                                                           ff_b2 + l * W, p_xd, p_xd,
                                                           1024, 256, 1, 1);
    }

    // decoder on cls rows
    k_dec<<<B_GR, 256>>>(ln_post_s, ln_post_b, dec_w1, dec_b1, dec_w2, dec_b2,
                         dec_w3, dec_b3, out);
    (void)in_sizes; (void)n_in; (void)out_size;
}

// round 6
// speedup vs baseline: 3.4023x; 1.0450x over previous
#include <cuda_runtime.h>
#include <math.h>
#include <stdint.h>

// ---------------- problem constants ----------------
#define N_NODES 16384
#define B_GR    64
#define NPG     256
#define E_EDGES 524288
#define F_IN    32
#define D_IN    56        // 32 + 3*8
#define W       256
#define S       257
#define HEADS   8
#define DH      32
#define DFF     1024
#define HID     512
#define OUT_D   64
#define LAYERS  2
#define MROWS   (B_GR * S)   // 16448
#define MPAD    16512        // 129 * 128

// ---------------- scratch (device globals; no allocs) ----------------
__device__ float g_xc  [N_NODES * D_IN];
__device__ float g_agg [N_NODES * D_IN];
__device__ float g_deg [N_NODES];
__device__ float g_xd  [MPAD * W];
__device__ float g_h1  [MPAD * W];
__device__ float g_qkv [MPAD * 3 * W];
__device__ float g_attn[MPAD * W];
__device__ float g_ff  [MPAD * DFF];
// transposed weights: per layer: qkvT(768*256) outT(256*256) ff1T(1024*256) ff2T(256*1024)
#define WT_LAYER 786432
#define WT_QKV   0
#define WT_OUT   196608
#define WT_FF1   262144
#define WT_FF2   524288
__device__ float g_wt [2 * WT_LAYER];

// ---------------- helpers ----------------
__device__ __forceinline__ float warp_sum(float v) {
#pragma unroll
    for (int o = 16; o > 0; o >>= 1) v += __shfl_xor_sync(0xffffffffu, v, o);
    return v;
}
__device__ __forceinline__ float block_sum256(float v, float* red) {
    __syncthreads();
    v = warp_sum(v);
    if ((threadIdx.x & 31) == 0) red[threadIdx.x >> 5] = v;
    __syncthreads();
    float r = 0.f;
#pragma unroll
    for (int i = 0; i < 8; i++) r += red[i];
    return r;
}
__device__ __forceinline__ float gelu_f(float x) {
    float u = 0.7978845608028654f * (x + 0.044715f * x * x * x);
    float t;
    asm("tanh.approx.f32 %0, %1;" : "=f"(t) : "f"(u));
    return 0.5f * x * (1.0f + t);
}
typedef unsigned long long ull;
__device__ __forceinline__ ull ffma2(ull a, ull b, ull c) {
    ull d;
    asm("fma.rn.f32x2 %0, %1, %2, %3;" : "=l"(d) : "l"(a), "l"(b), "l"(c));
    return d;
}
__device__ __forceinline__ ull mul2(ull a, ull b) {
    ull d;
    asm("mul.rn.f32x2 %0, %1, %2;" : "=l"(d) : "l"(a), "l"(b));
    return d;
}
__device__ __forceinline__ ull pack2(float x) {
    ull d;
    asm("mov.b64 %0, {%1, %1};" : "=l"(d) : "f"(x));
    return d;
}
__device__ __forceinline__ float lo2(ull v) { return __uint_as_float((unsigned)(v & 0xffffffffull)); }
__device__ __forceinline__ float hi2(ull v) { return __uint_as_float((unsigned)(v >> 32)); }

__device__ __forceinline__ uint32_t s2u(const void* p) {
    uint32_t a;
    asm("{ .reg .u64 t; cvta.to.shared.u64 t, %1; cvt.u32.u64 %0, t; }" : "=r"(a) : "l"(p));
    return a;
}
__device__ __forceinline__ void cp16(uint32_t dst, const void* src) {
    asm volatile("cp.async.cg.shared.global [%0], [%1], 16;" :: "r"(dst), "l"(src));
}
__device__ __forceinline__ void cp_commit() { asm volatile("cp.async.commit_group;" ::: "memory"); }
__device__ __forceinline__ void cp_wait1()  { asm volatile("cp.async.wait_group 1;" ::: "memory"); }

__device__ __forceinline__ float tf32r(float f) {
    uint32_t r;
    asm("cvt.rna.tf32.f32 %0, %1;" : "=r"(r) : "f"(f));
    return __uint_as_float(r);
}
__device__ __forceinline__ void mma_tf32(float* d, const uint32_t* a, const uint32_t* b) {
    asm volatile(
        "mma.sync.aligned.m16n8k8.row.col.f32.tf32.tf32.f32 "
        "{%0,%1,%2,%3}, {%4,%5,%6,%7}, {%8,%9}, {%0,%1,%2,%3};"
        : "+f"(d[0]), "+f"(d[1]), "+f"(d[2]), "+f"(d[3])
        : "r"(a[0]), "r"(a[1]), "r"(a[2]), "r"(a[3]), "r"(b[0]), "r"(b[1]));
}

// ---------------- fused: PE + deg init + ALL weight transposes ----------------
#define PE_BLOCKS 3584   // N_NODES * D_IN / 256
__global__ void __launch_bounds__(256) k_pe_tr(const float* __restrict__ x,
                                               const float* __restrict__ p,
                                               const float* __restrict__ ipw,
                                               const float* __restrict__ opw,
                                               const float* __restrict__ f1w,
                                               const float* __restrict__ f2w) {
    if (blockIdx.x < PE_BLOCKS) {
        int i = blockIdx.x * 256 + threadIdx.x;
        if (i < N_NODES) g_deg[i] = 1.0f;  // self loop
        int n = i / D_IN, j = i - n * D_IN;
        float v;
        if (j < F_IN) {
            v = x[n * F_IN + j];
        } else {
            int jj = j - F_IN;
            int d = jj >> 3, f = jj & 7;
            float freq = 3.14159265358979323846f * (float)(1 << f);
            v = sinf(p[n * 3 + d] * freq);
        }
        g_xc[i] = v;
        return;
    }
    // transpose part: dst[N,K] = tf32(src[K,N]^T)
    int b2 = blockIdx.x - PE_BLOCKS;
    int layer = b2 / 768;
    int r = b2 - layer * 768;
    const float* src;
    float* dst;
    int K, N, tile, nx;
    if (r < 192)      { src = ipw + (size_t)layer * W * 768;  dst = g_wt + (size_t)layer * WT_LAYER + WT_QKV; K = 256; N = 768;  tile = r;       nx = 24; }
    else if (r < 256) { src = opw + (size_t)layer * W * W;    dst = g_wt + (size_t)layer * WT_LAYER + WT_OUT; K = 256; N = 256;  tile = r - 192; nx = 8;  }
    else if (r < 512) { src = f1w + (size_t)layer * W * DFF;  dst = g_wt + (size_t)layer * WT_LAYER + WT_FF1; K = 256; N = 1024; tile = r - 256; nx = 32; }
    else              { src = f2w + (size_t)layer * DFF * W;  dst = g_wt + (size_t)layer * WT_LAYER + WT_FF2; K = 1024; N = 256; tile = r - 512; nx = 8;  }
    int bx = (tile % nx) * 32, by = (tile / nx) * 32;
    __shared__ float tl[32][33];
    int tx = threadIdx.x & 31, ty = threadIdx.x >> 5;  // 32x8
#pragma unroll
    for (int j = 0; j < 32; j += 8)
        tl[ty + j][tx] = src[(size_t)(by + ty + j) * N + bx + tx];
    __syncthreads();
#pragma unroll
    for (int j = 0; j < 32; j += 8)
        dst[(size_t)(bx + ty + j) * K + by + tx] = tf32r(tl[tx][ty + j]);
}

// ---------------- stage 2: degree / scatter ----------------
__global__ void k_deg_count(const int* __restrict__ ei) {
    int e = blockIdx.x * blockDim.x + threadIdx.x;
    if (e < E_EDGES) atomicAdd(&g_deg[ei[E_EDGES + e]], 1.0f);
}
__global__ void k_agg_init() {
    int i = blockIdx.x * blockDim.x + threadIdx.x;
    if (i >= N_NODES * D_IN) return;
    int n = i / D_IN;
    float d = rsqrtf(fmaxf(g_deg[n], 1e-12f));
    g_agg[i] = d * d * g_xc[i];
}
__global__ void k_scatter(const int* __restrict__ ei) {
    int i = blockIdx.x * blockDim.x + threadIdx.x;  // E*64 total
    int e = i >> 6, j = i & 63;
    if (j >= D_IN) return;
    int r = ei[e];
    int c = ei[E_EDGES + e];
    float coef = rsqrtf(fmaxf(g_deg[r], 1e-12f)) * rsqrtf(fmaxf(g_deg[c], 1e-12f));
    atomicAdd(&g_agg[c * D_IN + j], coef * g_xc[r * D_IN + j]);
}

// ---------------- stage 3: GCN matvec + ln_pre + layer0 norm1 LN ----------------
__global__ void __launch_bounds__(256) k_gcn(const float* __restrict__ w,
                                             const float* __restrict__ bias,
                                             const float* __restrict__ cls_tok,
                                             const float* __restrict__ lns,
                                             const float* __restrict__ lnb,
                                             const float* __restrict__ n1s,
                                             const float* __restrict__ n1b) {
    int blk = blockIdx.x;
    int t = threadIdx.x;
    __shared__ float a[D_IN];
    __shared__ float red[8];
    float acc;
    size_t dst;
    if (blk < N_NODES) {
        int n = blk;
        if (t < D_IN) a[t] = g_agg[n * D_IN + t];
        __syncthreads();
        acc = bias[t];
#pragma unroll
        for (int i = 0; i < D_IN; i++) acc += a[i] * w[i * W + t];
        int b = n / NPG, pos = n - b * NPG;
        dst = (size_t)(b * S + pos + 1) * W + t;
    } else {
        acc = cls_tok[t];
        dst = (size_t)(blk - N_NODES) * S * W + t;
    }
    float s1 = block_sum256(acc, red);
    float s2 = block_sum256(acc * acc, red);
    float m = s1 * (1.0f / W);
    float var = s2 * (1.0f / W) - m * m;
    float o = (acc - m) * rsqrtf(var + 1e-5f) * lns[t] + lnb[t];
    g_xd[dst] = o;
    // layer-0 norm1 LN fused
    float t1 = block_sum256(o, red);
    float t2 = block_sum256(o * o, red);
    float mb = t1 * (1.0f / W);
    float vb = t2 * (1.0f / W) - mb * mb;
    g_h1[dst] = tf32r((o - mb) * rsqrtf(vb + 1e-5f) * n1s[t] + n1b[t]);
}

// ---------------- LayerNorm rows: g_xd -> g_h1 (tf32-rounded) ----------------
__global__ void __launch_bounds__(256) k_ln(const float* __restrict__ s,
                                            const float* __restrict__ b) {
    int row = blockIdx.x, t = threadIdx.x;
    __shared__ float red[8];
    float v = g_xd[(size_t)row * W + t];
    float s1 = block_sum256(v, red);
    float s2 = block_sum256(v * v, red);
    float m = s1 * (1.0f / W);
    float var = s2 * (1.0f / W) - m * m;
    g_h1[(size_t)row * W + t] = tf32r((v - m) * rsqrtf(var + 1e-5f) * s[t] + b[t]);
}

// ---------------- tf32 mma.sync GEMM (operands pre-rounded to tf32) ----------------
// C[M,N] = [Res +] act(A[M,K] * Bt[N,K]^T + bias). Tiles 128x128, Kc=32,
// 256 threads = 8 warps (4m x 2n), warp tile 32x64 = 2x8 mma(m16n8k8).
// dyn smem floats: As[2][128][36] at 0, Bs[2][128][36] at 9216. 73728 bytes.
#define KC 32
#define SROW 36
__device__ __forceinline__ void mmg_load(uint32_t smb, const float* A, const float* Bt,
                                         int bm, int bn, int K, int s, int b, int t) {
    int k0 = s * KC;
    const float* Ag = A + (size_t)bm * K + k0;
    const float* Bg = Bt + (size_t)bn * K + k0;
    uint32_t abase = smb + (uint32_t)(b * 4608) * 4;
    uint32_t bbase = smb + (uint32_t)(9216 + b * 4608) * 4;
#pragma unroll
    for (int i = 0; i < 4; i++) {
        int q = t + i * 256;          // 0..1023
        int row = q >> 3, kq = (q & 7) * 4;
        uint32_t off = (uint32_t)(row * SROW + kq) * 4;
        size_t g = (size_t)row * K + kq;
        cp16(abase + off, Ag + g);
        cp16(bbase + off, Bg + g);
    }
}

__global__ void __launch_bounds__(256, 2) k_gemm_mma(const float* __restrict__ A,
                                                     const float* __restrict__ Bt,
                                                     const float* __restrict__ bias,
                                                     const float* __restrict__ Res,
                                                     float* __restrict__ C,
                                                     int K, int Nn, int act, int has_res,
                                                     int rnd) {
    extern __shared__ __align__(16) float smf[];
    uint32_t smb = s2u(smf);
    int bm = blockIdx.y * 128, bn = blockIdx.x * 128;
    int t = threadIdx.x;
    int wid = t >> 5, lane = t & 31;
    int g = lane >> 2, tig = lane & 3;
    int wm = wid & 3, wn = wid >> 2;          // 4 x 2 warp grid

    float acc[2][8][4];
#pragma unroll
    for (int mt = 0; mt < 2; mt++)
#pragma unroll
        for (int nt = 0; nt < 8; nt++)
#pragma unroll
            for (int i = 0; i < 4; i++) acc[mt][nt][i] = 0.f;

    const int T = K / KC;
    mmg_load(smb, A, Bt, bm, bn, K, 0, 0, t);
    cp_commit();
    mmg_load(smb, A, Bt, bm, bn, K, 1, 1, t);
    cp_commit();

    for (int s = 0; s < T; s++) {
        int b = s & 1;
        cp_wait1();
        __syncthreads();
        const uint32_t* sA = (const uint32_t*)(smf + b * 4608);
        const uint32_t* sB = (const uint32_t*)(smf + 9216 + b * 4608);
#pragma unroll
        for (int kk = 0; kk < 4; kk++) {
            int k8 = kk * 8;
            uint32_t afr[2][4];
#pragma unroll
            for (int mt = 0; mt < 2; mt++) {
                int m0 = wm * 32 + mt * 16 + g;
                const uint32_t* ap = sA + m0 * SROW + k8 + tig;
                afr[mt][0] = ap[0];
                afr[mt][1] = ap[8 * SROW];
                afr[mt][2] = ap[4];
                afr[mt][3] = ap[8 * SROW + 4];
            }
            uint32_t bfr[8][2];
#pragma unroll
            for (int nt = 0; nt < 8; nt++) {
                int n0 = wn * 64 + nt * 8 + g;
                const uint32_t* bp = sB + n0 * SROW + k8 + tig;
                bfr[nt][0] = bp[0];
                bfr[nt][1] = bp[4];
            }
#pragma unroll
            for (int mt = 0; mt < 2; mt++)
#pragma unroll
                for (int nt = 0; nt < 8; nt++)
                    mma_tf32(acc[mt][nt], afr[mt], bfr[nt]);
        }
        __syncthreads();
        if (s + 2 < T) mmg_load(smb, A, Bt, bm, bn, K, s + 2, b, t);
        cp_commit();
    }

    // epilogue
#pragma unroll
    for (int mt = 0; mt < 2; mt++) {
        int row0 = bm + wm * 32 + mt * 16 + g;
#pragma unroll
        for (int nt = 0; nt < 8; nt++) {
            int col = bn + wn * 64 + nt * 8 + 2 * tig;
            float2 bb = *(const float2*)&bias[col];
#pragma unroll
            for (int h = 0; h < 2; h++) {
                int row = row0 + h * 8;
                float v0 = acc[mt][nt][2 * h + 0] + bb.x;
                float v1 = acc[mt][nt][2 * h + 1] + bb.y;
                if (act == 1) { v0 = gelu_f(v0); v1 = gelu_f(v1); }
                if (has_res) {
                    float2 r = *(const float2*)&Res[(size_t)row * Nn + col];
                    v0 += r.x; v1 += r.y;
                }
                if (rnd) { v0 = tf32r(v0); v1 = tf32r(v1); }
                *(float2*)&C[(size_t)row * Nn + col] = make_float2(v0, v1);
            }
        }
    }
}

// ---------------- attention: one thread = one query row, flash-style ----------------
__global__ void __launch_bounds__(288) k_attn() {
    extern __shared__ float sm[];
    float* Ks = sm;            // S*32
    float* Vs = sm + S * DH;   // S*32

    int bh = blockIdx.x;
    int b = bh >> 3, h = bh & 7;
    int t = threadIdx.x;
    const float* base = g_qkv + (size_t)b * S * 768;

    for (int idx = t; idx < S * 8; idx += 288) {
        int s_ = idx >> 3, d4 = idx & 7;
        const float* src = base + (size_t)s_ * 768 + h * 32 + d4 * 4;
        ((float4*)Ks)[idx] = *(const float4*)(src + 256);
        ((float4*)Vs)[idx] = *(const float4*)(src + 512);
    }
    __syncthreads();
    if (t > 256) return;

    int q = t;
    ull qv[16];
    {
        const ull* qp = (const ull*)(base + (size_t)q * 768 + h * 32);
#pragma unroll
        for (int i = 0; i < 16; i++) qv[i] = qp[i];
    }
    ull o[16];
#pragma unroll
    for (int i = 0; i < 16; i++) o[i] = 0ull;
    float m = -1e30f, l = 0.f;
    const float scale = 0.17677669529663687f;  // 1/sqrt(32)
    int kmax = (q == 0) ? 256 : q;

    for (int k = 0; k <= kmax; k++) {
        const ull* kr = (const ull*)&Ks[k * DH];
        ull sacc = 0ull;
#pragma unroll
        for (int i = 0; i < 16; i++) sacc = ffma2(qv[i], kr[i], sacc);
        float s = (lo2(sacc) + hi2(sacc)) * scale;
        float mn = fmaxf(m, s);
        float c = __expf(m - mn);
        float e = __expf(s - mn);
        l = l * c + e;
        ull c2 = pack2(c), e2 = pack2(e);
        const ull* vr = (const ull*)&Vs[k * DH];
#pragma unroll
        for (int i = 0; i < 16; i++) o[i] = ffma2(e2, vr[i], mul2(o[i], c2));
        m = mn;
    }
    float inv = 1.0f / l;
    float* op = g_attn + ((size_t)b * S + q) * W + h * 32;
#pragma unroll
    for (int i = 0; i < 16; i++) {
        float2 v = make_float2(tf32r(lo2(o[i]) * inv), tf32r(hi2(o[i]) * inv));
        *(float2*)&op[i * 2] = v;
    }
}

// ---------------- decoder (fused, one block per graph) ----------------
__global__ void __launch_bounds__(256) k_dec(const float* __restrict__ lns,
                                             const float* __restrict__ lnb,
                                             const float* __restrict__ w1,
                                             const float* __restrict__ b1,
                                             const float* __restrict__ w2,
                                             const float* __restrict__ b2,
                                             const float* __restrict__ w3,
                                             const float* __restrict__ b3,
                                             float* __restrict__ outp) {
    int b = blockIdx.x, t = threadIdx.x;
    __shared__ float cls[W];
    __shared__ float h1[HID];
    __shared__ float h2[HID];
    __shared__ float red[8];
    float v = g_xd[(size_t)b * S * W + t];
    float s1 = block_sum256(v, red);
    float s2 = block_sum256(v * v, red);
    float m = s1 * (1.0f / W);
    float var = s2 * (1.0f / W) - m * m;
    cls[t] = (v - m) * rsqrtf(var + 1e-5f) * lns[t] + lnb[t];
    __syncthreads();
    for (int j = t; j < HID; j += 256) {
        float a = b1[j];
#pragma unroll 8
        for (int i = 0; i < W; i++) a += cls[i] * w1[i * HID + j];
        h1[j] = fmaxf(a, 0.f);
    }
    __syncthreads();
    for (int j = t; j < HID; j += 256) {
        float a = b2[j];
#pragma unroll 8
        for (int i = 0; i < HID; i++) a += h1[i] * w2[i * HID + j];
        h2[j] = fmaxf(a, 0.f);
    }
    __syncthreads();
    if (t < OUT_D) {
        float a = b3[t];
#pragma unroll 8
        for (int i = 0; i < HID; i++) a += h2[i] * w3[i * OUT_D + t];
        outp[b * OUT_D + t] = fmaxf(a, 0.f);
    }
}

// ---------------- launch ----------------
extern "C" void kernel_launch(void* const* d_in, const int* in_sizes, int n_in,
                              void* d_out, int out_size) {
    const float* x          = (const float*)d_in[0];
    const float* p          = (const float*)d_in[1];
    const int*   edge_index = (const int*)d_in[2];
    // d_in[3] = batch (structure known: arange(N)//NPG) — unused
    const float* gcn_w      = (const float*)d_in[4];
    const float* gcn_b      = (const float*)d_in[5];
    const float* cls_token  = (const float*)d_in[6];
    const float* ln_pre_s   = (const float*)d_in[7];
    const float* ln_pre_b   = (const float*)d_in[8];
    const float* norm1_s    = (const float*)d_in[9];
    const float* norm1_b    = (const float*)d_in[10];
    const float* in_proj_w  = (const float*)d_in[11];
    const float* in_proj_b  = (const float*)d_in[12];
    const float* out_proj_w = (const float*)d_in[13];
    const float* out_proj_b = (const float*)d_in[14];
    const float* norm2_s    = (const float*)d_in[15];
    const float* norm2_b    = (const float*)d_in[16];
    const float* ff_w1      = (const float*)d_in[17];
    const float* ff_b1      = (const float*)d_in[18];
    const float* ff_w2      = (const float*)d_in[19];
    const float* ff_b2      = (const float*)d_in[20];
    const float* ln_post_s  = (const float*)d_in[21];
    const float* ln_post_b  = (const float*)d_in[22];
    const float* dec_w1     = (const float*)d_in[23];
    const float* dec_b1     = (const float*)d_in[24];
    const float* dec_w2     = (const float*)d_in[25];
    const float* dec_b2     = (const float*)d_in[26];
    const float* dec_w3     = (const float*)d_in[27];
    const float* dec_b3     = (const float*)d_in[28];
    float* out = (float*)d_out;

    float *p_h1, *p_qkv, *p_attn, *p_ff, *p_xd, *p_wt;
    cudaGetSymbolAddress((void**)&p_h1, g_h1);
    cudaGetSymbolAddress((void**)&p_qkv, g_qkv);
    cudaGetSymbolAddress((void**)&p_attn, g_attn);
    cudaGetSymbolAddress((void**)&p_ff, g_ff);
    cudaGetSymbolAddress((void**)&p_xd, g_xd);
    cudaGetSymbolAddress((void**)&p_wt, g_wt);

    const int attn_smem = 2 * S * DH * 4;  // 65792
    cudaFuncSetAttribute(k_attn, cudaFuncAttributeMaxDynamicSharedMemorySize, attn_smem);
    const int mma_smem = 73728;
    cudaFuncSetAttribute(k_gemm_mma, cudaFuncAttributeMaxDynamicSharedMemorySize, mma_smem);

    // front-end (launch order tuned so ncu -s 5 captures the QKV GEMM)
    k_pe_tr<<<PE_BLOCKS + 2 * 768, 256>>>(x, p, in_proj_w, out_proj_w, ff_w1, ff_w2);
    k_deg_count<<<E_EDGES / 256, 256>>>(edge_index);
    k_agg_init<<<(N_NODES * D_IN + 255) / 256, 256>>>();
    k_scatter<<<(E_EDGES * 64) / 256, 256>>>(edge_index);
    k_gcn<<<N_NODES + B_GR, 256>>>(gcn_w, gcn_b, cls_token, ln_pre_s, ln_pre_b,
                                   norm1_s, norm1_b);

    // transformer layers
    for (int l = 0; l < LAYERS; l++) {
        float* wl = p_wt + (size_t)l * WT_LAYER;
        if (l > 0) k_ln<<<MROWS, 256>>>(norm1_s + l * W, norm1_b + l * W);
        k_gemm_mma<<<dim3(6, MPAD / 128), 256, mma_smem>>>(p_h1, wl + WT_QKV,
                                                           in_proj_b + l * 3 * W, nullptr, p_qkv,
                                                           256, 768, 0, 0, 0);
        k_attn<<<B_GR * HEADS, 288, attn_smem>>>();
        k_gemm_mma<<<dim3(2, MPAD / 128), 256, mma_smem>>>(p_attn, wl + WT_OUT,
                                                           out_proj_b + l * W, p_xd, p_xd,
                                                           256, 256, 0, 1, 0);
        k_ln<<<MROWS, 256>>>(norm2_s + l * W, norm2_b + l * W);
        k_gemm_mma<<<dim3(8, MPAD / 128), 256, mma_smem>>>(p_h1, wl + WT_FF1,
                                                           ff_b1 + l * DFF, nullptr, p_ff,
                                                           256, 1024, 1, 0, 1);
        k_gemm_mma<<<dim3(2, MPAD / 128), 256, mma_smem>>>(p_ff, wl + WT_FF2,
                                                           ff_b2 + l * W, p_xd, p_xd,
                                                           1024, 256, 1, 1, 0);
    }

    // decoder on cls rows
    k_dec<<<B_GR, 256>>>(ln_post_s, ln_post_b, dec_w1, dec_b1, dec_w2, dec_b2,
                         dec_w3, dec_b3, out);
    (void)in_sizes; (void)n_in; (void)out_size;
}

// round 7
// speedup vs baseline: 4.3277x; 1.2720x over previous
#include <cuda_runtime.h>
#include <cuda_fp16.h>
#include <math.h>
#include <stdint.h>

// ---------------- problem constants ----------------
#define N_NODES 16384
#define B_GR    64
#define NPG     256
#define E_EDGES 524288
#define F_IN    32
#define D_IN    56        // 32 + 3*8
#define W       256
#define S       257
#define HEADS   8
#define DH      32
#define DFF     1024
#define HID     512
#define OUT_D   64
#define LAYERS  2
#define MROWS   (B_GR * S)   // 16448
#define MPAD    16512        // 129 * 128

// ---------------- scratch (device globals; no allocs) ----------------
__device__ float  g_xc  [N_NODES * D_IN];
__device__ float  g_agg [N_NODES * D_IN];
__device__ float  g_deg [N_NODES];
__device__ float  g_xd  [MPAD * W];
__device__ float  g_qkv [MPAD * 3 * W];
__device__ __half g_h1h [MPAD * W];
__device__ __half g_atth[MPAD * W];
__device__ __half g_ffh [MPAD * DFF];
// transposed weights (half): per layer qkvT(768*256) outT(256*256) ff1T(1024*256) ff2T(256*1024)
#define WT_LAYER 786432
#define WT_QKV   0
#define WT_OUT   196608
#define WT_FF1   262144
#define WT_FF2   524288
__device__ __half g_wth[2 * WT_LAYER];

// ---------------- helpers ----------------
__device__ __forceinline__ float warp_sum(float v) {
#pragma unroll
    for (int o = 16; o > 0; o >>= 1) v += __shfl_xor_sync(0xffffffffu, v, o);
    return v;
}
__device__ __forceinline__ float block_sum256(float v, float* red) {
    __syncthreads();
    v = warp_sum(v);
    if ((threadIdx.x & 31) == 0) red[threadIdx.x >> 5] = v;
    __syncthreads();
    float r = 0.f;
#pragma unroll
    for (int i = 0; i < 8; i++) r += red[i];
    return r;
}
__device__ __forceinline__ float gelu_f(float x) {
    float u = 0.7978845608028654f * (x + 0.044715f * x * x * x);
    float t;
    asm("tanh.approx.f32 %0, %1;" : "=f"(t) : "f"(u));
    return 0.5f * x * (1.0f + t);
}
typedef unsigned long long ull;
__device__ __forceinline__ ull ffma2(ull a, ull b, ull c) {
    ull d;
    asm("fma.rn.f32x2 %0, %1, %2, %3;" : "=l"(d) : "l"(a), "l"(b), "l"(c));
    return d;
}
__device__ __forceinline__ ull mul2(ull a, ull b) {
    ull d;
    asm("mul.rn.f32x2 %0, %1, %2;" : "=l"(d) : "l"(a), "l"(b));
    return d;
}
__device__ __forceinline__ ull pack2(float x) {
    ull d;
    asm("mov.b64 %0, {%1, %1};" : "=l"(d) : "f"(x));
    return d;
}
__device__ __forceinline__ float lo2(ull v) { return __uint_as_float((unsigned)(v & 0xffffffffull)); }
__device__ __forceinline__ float hi2(ull v) { return __uint_as_float((unsigned)(v >> 32)); }

__device__ __forceinline__ uint32_t s2u(const void* p) {
    uint32_t a;
    asm("{ .reg .u64 t; cvta.to.shared.u64 t, %1; cvt.u32.u64 %0, t; }" : "=r"(a) : "l"(p));
    return a;
}
__device__ __forceinline__ void cp16(uint32_t dst, const void* src) {
    asm volatile("cp.async.cg.shared.global [%0], [%1], 16;" :: "r"(dst), "l"(src));
}
__device__ __forceinline__ void cp_commit() { asm volatile("cp.async.commit_group;" ::: "memory"); }
__device__ __forceinline__ void cp_wait1()  { asm volatile("cp.async.wait_group 1;" ::: "memory"); }

__device__ __forceinline__ void mma_f16(float* d, const uint32_t* a, const uint32_t* b) {
    asm volatile(
        "mma.sync.aligned.m16n8k16.row.col.f32.f16.f16.f32 "
        "{%0,%1,%2,%3}, {%4,%5,%6,%7}, {%8,%9}, {%0,%1,%2,%3};"
        : "+f"(d[0]), "+f"(d[1]), "+f"(d[2]), "+f"(d[3])
        : "r"(a[0]), "r"(a[1]), "r"(a[2]), "r"(a[3]), "r"(b[0]), "r"(b[1]));
}
__device__ __forceinline__ void red4(float* addr, float4 v) {
    asm volatile("red.global.add.v4.f32 [%0], {%1,%2,%3,%4};"
                 :: "l"(addr), "f"(v.x), "f"(v.y), "f"(v.z), "f"(v.w) : "memory");
}

// ---------------- fused: PE + deg init + ALL weight transposes (fp32 -> half) ----------------
#define PE_BLOCKS 3584   // N_NODES * D_IN / 256
__global__ void __launch_bounds__(256) k_pe_tr(const float* __restrict__ x,
                                               const float* __restrict__ p,
                                               const float* __restrict__ ipw,
                                               const float* __restrict__ opw,
                                               const float* __restrict__ f1w,
                                               const float* __restrict__ f2w) {
    if (blockIdx.x < PE_BLOCKS) {
        int i = blockIdx.x * 256 + threadIdx.x;
        if (i < N_NODES) g_deg[i] = 1.0f;  // self loop
        int n = i / D_IN, j = i - n * D_IN;
        float v;
        if (j < F_IN) {
            v = x[n * F_IN + j];
        } else {
            int jj = j - F_IN;
            int d = jj >> 3, f = jj & 7;
            float freq = 3.14159265358979323846f * (float)(1 << f);
            v = sinf(p[n * 3 + d] * freq);
        }
        g_xc[i] = v;
        return;
    }
    // transpose part: dst[N,K] = half(src[K,N]^T)
    int b2 = blockIdx.x - PE_BLOCKS;
    int layer = b2 / 768;
    int r = b2 - layer * 768;
    const float* src;
    __half* dst;
    int K, N, tile, nx;
    if (r < 192)      { src = ipw + (size_t)layer * W * 768;  dst = g_wth + (size_t)layer * WT_LAYER + WT_QKV; K = 256; N = 768;  tile = r;       nx = 24; }
    else if (r < 256) { src = opw + (size_t)layer * W * W;    dst = g_wth + (size_t)layer * WT_LAYER + WT_OUT; K = 256; N = 256;  tile = r - 192; nx = 8;  }
    else if (r < 512) { src = f1w + (size_t)layer * W * DFF;  dst = g_wth + (size_t)layer * WT_LAYER + WT_FF1; K = 256; N = 1024; tile = r - 256; nx = 32; }
    else              { src = f2w + (size_t)layer * DFF * W;  dst = g_wth + (size_t)layer * WT_LAYER + WT_FF2; K = 1024; N = 256; tile = r - 512; nx = 8;  }
    int bx = (tile % nx) * 32, by = (tile / nx) * 32;
    __shared__ float tl[32][33];
    int tx = threadIdx.x & 31, ty = threadIdx.x >> 5;  // 32x8
#pragma unroll
    for (int j = 0; j < 32; j += 8)
        tl[ty + j][tx] = src[(size_t)(by + ty + j) * N + bx + tx];
    __syncthreads();
#pragma unroll
    for (int j = 0; j < 32; j += 8)
        dst[(size_t)(bx + ty + j) * K + by + tx] = __float2half_rn(tl[tx][ty + j]);
}

// ---------------- stage 2: degree / scatter ----------------
__global__ void k_deg_count(const int* __restrict__ ei) {
    int e = blockIdx.x * blockDim.x + threadIdx.x;
    if (e < E_EDGES) atomicAdd(&g_deg[ei[E_EDGES + e]], 1.0f);
}
__global__ void k_agg_init() {
    int i = blockIdx.x * blockDim.x + threadIdx.x;
    if (i >= N_NODES * D_IN) return;
    int n = i / D_IN;
    float d = rsqrtf(fmaxf(g_deg[n], 1e-12f));
    g_agg[i] = d * d * g_xc[i];
}
// one edge handled by 16 threads (14 active), float4 vector reductions
__global__ void k_scatter(const int* __restrict__ ei) {
    int i = blockIdx.x * blockDim.x + threadIdx.x;  // E*16 total
    int e = i >> 4, j = i & 15;
    if (j >= 14) return;
    int r = ei[e];
    int c = ei[E_EDGES + e];
    float coef = rsqrtf(fmaxf(g_deg[r], 1e-12f)) * rsqrtf(fmaxf(g_deg[c], 1e-12f));
    float4 v = *((const float4*)g_xc + (size_t)r * 14 + j);
    v.x *= coef; v.y *= coef; v.z *= coef; v.w *= coef;
    red4(g_agg + (size_t)c * D_IN + j * 4, v);
}

// ---------------- stage 3: GCN matvec + ln_pre + layer0 norm1 LN ----------------
__global__ void __launch_bounds__(256) k_gcn(const float* __restrict__ w,
                                             const float* __restrict__ bias,
                                             const float* __restrict__ cls_tok,
                                             const float* __restrict__ lns,
                                             const float* __restrict__ lnb,
                                             const float* __restrict__ n1s,
                                             const float* __restrict__ n1b) {
    int blk = blockIdx.x;
    int t = threadIdx.x;
    __shared__ float a[D_IN];
    __shared__ float red[8];
    float acc;
    size_t dst;
    if (blk < N_NODES) {
        int n = blk;
        if (t < D_IN) a[t] = g_agg[n * D_IN + t];
        __syncthreads();
        acc = bias[t];
#pragma unroll
        for (int i = 0; i < D_IN; i++) acc += a[i] * w[i * W + t];
        int b = n / NPG, pos = n - b * NPG;
        dst = (size_t)(b * S + pos + 1) * W + t;
    } else {
        acc = cls_tok[t];
        dst = (size_t)(blk - N_NODES) * S * W + t;
    }
    float s1 = block_sum256(acc, red);
    float s2 = block_sum256(acc * acc, red);
    float m = s1 * (1.0f / W);
    float var = s2 * (1.0f / W) - m * m;
    float o = (acc - m) * rsqrtf(var + 1e-5f) * lns[t] + lnb[t];
    g_xd[dst] = o;
    // layer-0 norm1 LN fused
    float t1 = block_sum256(o, red);
    float t2 = block_sum256(o * o, red);
    float mb = t1 * (1.0f / W);
    float vb = t2 * (1.0f / W) - mb * mb;
    g_h1h[dst] = __float2half_rn((o - mb) * rsqrtf(vb + 1e-5f) * n1s[t] + n1b[t]);
}

// ---------------- LayerNorm rows: g_xd -> g_h1h (half) ----------------
__global__ void __launch_bounds__(256) k_ln(const float* __restrict__ s,
                                            const float* __restrict__ b) {
    int row = blockIdx.x, t = threadIdx.x;
    __shared__ float red[8];
    float v = g_xd[(size_t)row * W + t];
    float s1 = block_sum256(v, red);
    float s2 = block_sum256(v * v, red);
    float m = s1 * (1.0f / W);
    float var = s2 * (1.0f / W) - m * m;
    g_h1h[(size_t)row * W + t] = __float2half_rn((v - m) * rsqrtf(var + 1e-5f) * s[t] + b[t]);
}

// ---------------- fp16 mma.sync GEMM ----------------
// C[M,N] = [Res +] act(A[M,K] * Bt[N,K]^T + bias), A/Bt half, fp32 accum.
// Tiles 128x128, Kc=64, 256 threads = 8 warps (4m x 2n), warp tile 32x64,
// per kk(=k16) 2x8 mma(m16n8k16). smem: A[2][128][72]h, B[2][128][72]h = 73728 B.
#define KCH 64
#define SRH 72
__device__ __forceinline__ void hload(uint32_t smb, const __half* A, const __half* Bt,
                                      int bm, int bn, int K, int s, int b, int t) {
    int k0 = s * KCH;
    const __half* Ag = A + (size_t)bm * K + k0;
    const __half* Bg = Bt + (size_t)bn * K + k0;
    uint32_t ab = smb + (uint32_t)b * 18432u;
    uint32_t bb = smb + 36864u + (uint32_t)b * 18432u;
#pragma unroll
    for (int i = 0; i < 4; i++) {
        int q = t + i * 256;          // 0..1023
        int row = q >> 3, c = q & 7;
        uint32_t off = (uint32_t)(row * 144 + c * 16);
        size_t g = (size_t)row * K + c * 8;
        cp16(ab + off, Ag + g);
        cp16(bb + off, Bg + g);
    }
}

__global__ void __launch_bounds__(256, 2) k_gemm_h(const __half* __restrict__ A,
                                                   const __half* __restrict__ Bt,
                                                   const float* __restrict__ bias,
                                                   const float* __restrict__ Res,
                                                   float* __restrict__ Cf,
                                                   __half* __restrict__ Ch,
                                                   int K, int Nn, int act, int has_res,
                                                   int out_half) {
    extern __shared__ __align__(16) char smc[];
    uint32_t smb = s2u(smc);
    const __half* smh = (const __half*)smc;
    int bm = blockIdx.y * 128, bn = blockIdx.x * 128;
    int t = threadIdx.x;
    int wid = t >> 5, lane = t & 31;
    int g = lane >> 2, tig = lane & 3;
    int wm = wid & 3, wn = wid >> 2;          // 4 x 2 warp grid

    float acc[2][8][4];
#pragma unroll
    for (int mt = 0; mt < 2; mt++)
#pragma unroll
        for (int nt = 0; nt < 8; nt++)
#pragma unroll
            for (int i = 0; i < 4; i++) acc[mt][nt][i] = 0.f;

    const int T = K / KCH;
    hload(smb, A, Bt, bm, bn, K, 0, 0, t);
    cp_commit();
    hload(smb, A, Bt, bm, bn, K, 1, 1, t);
    cp_commit();

    for (int s = 0; s < T; s++) {
        int b = s & 1;
        cp_wait1();
        __syncthreads();
        const __half* sA = smh + b * 9216;
        const __half* sB = smh + 18432 + b * 9216;
#pragma unroll
        for (int kk = 0; kk < 4; kk++) {
            int k16 = kk * 16;
            uint32_t afr[2][4];
#pragma unroll
            for (int mt = 0; mt < 2; mt++) {
                int m0 = wm * 32 + mt * 16 + g;
                const __half* ap = sA + m0 * SRH + k16 + 2 * tig;
                afr[mt][0] = *(const uint32_t*)(ap);
                afr[mt][1] = *(const uint32_t*)(ap + 8 * SRH);
                afr[mt][2] = *(const uint32_t*)(ap + 8);
                afr[mt][3] = *(const uint32_t*)(ap + 8 * SRH + 8);
            }
            uint32_t bfr[8][2];
#pragma unroll
            for (int nt = 0; nt < 8; nt++) {
                int n0 = wn * 64 + nt * 8 + g;
                const __half* bp = sB + n0 * SRH + k16 + 2 * tig;
                bfr[nt][0] = *(const uint32_t*)(bp);
                bfr[nt][1] = *(const uint32_t*)(bp + 8);
            }
#pragma unroll
            for (int mt = 0; mt < 2; mt++)
#pragma unroll
                for (int nt = 0; nt < 8; nt++)
                    mma_f16(acc[mt][nt], afr[mt], bfr[nt]);
        }
        __syncthreads();
        if (s + 2 < T) hload(smb, A, Bt, bm, bn, K, s + 2, b, t);
        cp_commit();
    }

    // epilogue: rows bm + wm*32 + mt*16 + g (+8), cols bn + wn*64 + nt*8 + 2*tig
#pragma unroll
    for (int mt = 0; mt < 2; mt++) {
        int row0 = bm + wm * 32 + mt * 16 + g;
#pragma unroll
        for (int nt = 0; nt < 8; nt++) {
            int col = bn + wn * 64 + nt * 8 + 2 * tig;
            float2 bb = *(const float2*)&bias[col];
#pragma unroll
            for (int h = 0; h < 2; h++) {
                int row = row0 + h * 8;
                float v0 = acc[mt][nt][2 * h + 0] + bb.x;
                float v1 = acc[mt][nt][2 * h + 1] + bb.y;
                if (act == 1) { v0 = gelu_f(v0); v1 = gelu_f(v1); }
                if (has_res) {
                    float2 r = *(const float2*)&Res[(size_t)row * Nn + col];
                    v0 += r.x; v1 += r.y;
                }
                if (out_half) {
                    *(__half2*)&Ch[(size_t)row * Nn + col] =
                        __floats2half2_rn(v0, v1);
                } else {
                    *(float2*)&Cf[(size_t)row * Nn + col] = make_float2(v0, v1);
                }
            }
        }
    }
}

// ---------------- attention: one thread = one query row, flash-style ----------------
__global__ void __launch_bounds__(288) k_attn() {
    extern __shared__ float sm[];
    float* Ks = sm;            // S*32
    float* Vs = sm + S * DH;   // S*32

    int bh = blockIdx.x;
    int b = bh >> 3, h = bh & 7;
    int t = threadIdx.x;
    const float* base = g_qkv + (size_t)b * S * 768;

    for (int idx = t; idx < S * 8; idx += 288) {
        int s_ = idx >> 3, d4 = idx & 7;
        const float* src = base + (size_t)s_ * 768 + h * 32 + d4 * 4;
        ((float4*)Ks)[idx] = *(const float4*)(src + 256);
        ((float4*)Vs)[idx] = *(const float4*)(src + 512);
    }
    __syncthreads();
    if (t > 256) return;

    int q = t;
    ull qv[16];
    {
        const ull* qp = (const ull*)(base + (size_t)q * 768 + h * 32);
#pragma unroll
        for (int i = 0; i < 16; i++) qv[i] = qp[i];
    }
    ull o[16];
#pragma unroll
    for (int i = 0; i < 16; i++) o[i] = 0ull;
    float m = -1e30f, l = 0.f;
    const float scale = 0.17677669529663687f;  // 1/sqrt(32)
    int kmax = (q == 0) ? 256 : q;

    for (int k = 0; k <= kmax; k++) {
        const ull* kr = (const ull*)&Ks[k * DH];
        ull sacc = 0ull;
#pragma unroll
        for (int i = 0; i < 16; i++) sacc = ffma2(qv[i], kr[i], sacc);
        float s = (lo2(sacc) + hi2(sacc)) * scale;
        float mn = fmaxf(m, s);
        float c = __expf(m - mn);
        float e = __expf(s - mn);
        l = l * c + e;
        ull c2 = pack2(c), e2 = pack2(e);
        const ull* vr = (const ull*)&Vs[k * DH];
#pragma unroll
        for (int i = 0; i < 16; i++) o[i] = ffma2(e2, vr[i], mul2(o[i], c2));
        m = mn;
    }
    float inv = 1.0f / l;
    __half* op = g_atth + ((size_t)b * S + q) * W + h * 32;
#pragma unroll
    for (int i = 0; i < 16; i++) {
        *(__half2*)&op[i * 2] = __floats2half2_rn(lo2(o[i]) * inv, hi2(o[i]) * inv);
    }
}

// ---------------- decoder (fused, one block per graph) ----------------
__global__ void __launch_bounds__(256) k_dec(const float* __restrict__ lns,
                                             const float* __restrict__ lnb,
                                             const float* __restrict__ w1,
                                             const float* __restrict__ b1,
                                             const float* __restrict__ w2,
                                             const float* __restrict__ b2,
                                             const float* __restrict__ w3,
                                             const float* __restrict__ b3,
                                             float* __restrict__ outp) {
    int b = blockIdx.x, t = threadIdx.x;
    __shared__ float cls[W];
    __shared__ float h1[HID];
    __shared__ float h2[HID];
    __shared__ float red[8];
    float v = g_xd[(size_t)b * S * W + t];
    float s1 = block_sum256(v, red);
    float s2 = block_sum256(v * v, red);
    float m = s1 * (1.0f / W);
    float var = s2 * (1.0f / W) - m * m;
    cls[t] = (v - m) * rsqrtf(var + 1e-5f) * lns[t] + lnb[t];
    __syncthreads();
    for (int j = t; j < HID; j += 256) {
        float a = b1[j];
#pragma unroll 8
        for (int i = 0; i < W; i++) a += cls[i] * w1[i * HID + j];
        h1[j] = fmaxf(a, 0.f);
    }
    __syncthreads();
    for (int j = t; j < HID; j += 256) {
        float a = b2[j];
#pragma unroll 8
        for (int i = 0; i < HID; i++) a += h1[i] * w2[i * HID + j];
        h2[j] = fmaxf(a, 0.f);
    }
    __syncthreads();
    if (t < OUT_D) {
        float a = b3[t];
#pragma unroll 8
        for (int i = 0; i < HID; i++) a += h2[i] * w3[i * OUT_D + t];
        outp[b * OUT_D + t] = fmaxf(a, 0.f);
    }
}

// ---------------- launch ----------------
extern "C" void kernel_launch(void* const* d_in, const int* in_sizes, int n_in,
                              void* d_out, int out_size) {
    const float* x          = (const float*)d_in[0];
    const float* p          = (const float*)d_in[1];
    const int*   edge_index = (const int*)d_in[2];
    // d_in[3] = batch (structure known: arange(N)//NPG) — unused
    const float* gcn_w      = (const float*)d_in[4];
    const float* gcn_b      = (const float*)d_in[5];
    const float* cls_token  = (const float*)d_in[6];
    const float* ln_pre_s   = (const float*)d_in[7];
    const float* ln_pre_b   = (const float*)d_in[8];
    const float* norm1_s    = (const float*)d_in[9];
    const float* norm1_b    = (const float*)d_in[10];
    const float* in_proj_w  = (const float*)d_in[11];
    const float* in_proj_b  = (const float*)d_in[12];
    const float* out_proj_w = (const float*)d_in[13];
    const float* out_proj_b = (const float*)d_in[14];
    const float* norm2_s    = (const float*)d_in[15];
    const float* norm2_b    = (const float*)d_in[16];
    const float* ff_w1      = (const float*)d_in[17];
    const float* ff_b1      = (const float*)d_in[18];
    const float* ff_w2      = (const float*)d_in[19];
    const float* ff_b2      = (const float*)d_in[20];
    const float* ln_post_s  = (const float*)d_in[21];
    const float* ln_post_b  = (const float*)d_in[22];
    const float* dec_w1     = (const float*)d_in[23];
    const float* dec_b1     = (const float*)d_in[24];
    const float* dec_w2     = (const float*)d_in[25];
    const float* dec_b2     = (const float*)d_in[26];
    const float* dec_w3     = (const float*)d_in[27];
    const float* dec_b3     = (const float*)d_in[28];
    float* out = (float*)d_out;

    float *p_qkv, *p_xd;
    __half *p_h1h, *p_atth, *p_ffh, *p_wth;
    cudaGetSymbolAddress((void**)&p_qkv, g_qkv);
    cudaGetSymbolAddress((void**)&p_xd, g_xd);
    cudaGetSymbolAddress((void**)&p_h1h, g_h1h);
    cudaGetSymbolAddress((void**)&p_atth, g_atth);
    cudaGetSymbolAddress((void**)&p_ffh, g_ffh);
    cudaGetSymbolAddress((void**)&p_wth, g_wth);

    const int attn_smem = 2 * S * DH * 4;  // 65792
    cudaFuncSetAttribute(k_attn, cudaFuncAttributeMaxDynamicSharedMemorySize, attn_smem);
    const int mma_smem = 73728;
    cudaFuncSetAttribute(k_gemm_h, cudaFuncAttributeMaxDynamicSharedMemorySize, mma_smem);

    // front-end
    k_pe_tr<<<PE_BLOCKS + 2 * 768, 256>>>(x, p, in_proj_w, out_proj_w, ff_w1, ff_w2);
    k_deg_count<<<E_EDGES / 256, 256>>>(edge_index);
    k_agg_init<<<(N_NODES * D_IN + 255) / 256, 256>>>();
    k_scatter<<<(E_EDGES * 16) / 256, 256>>>(edge_index);
    k_gcn<<<N_NODES + B_GR, 256>>>(gcn_w, gcn_b, cls_token, ln_pre_s, ln_pre_b,
                                   norm1_s, norm1_b);

    // transformer layers
    for (int l = 0; l < LAYERS; l++) {
        __half* wl = p_wth + (size_t)l * WT_LAYER;
        if (l > 0) k_ln<<<MROWS, 256>>>(norm1_s + l * W, norm1_b + l * W);
        k_gemm_h<<<dim3(6, MPAD / 128), 256, mma_smem>>>(p_h1h, wl + WT_QKV,
                                                         in_proj_b + l * 3 * W, nullptr,
                                                         p_qkv, nullptr,
                                                         256, 768, 0, 0, 0);
        k_attn<<<B_GR * HEADS, 288, attn_smem>>>();
        k_gemm_h<<<dim3(2, MPAD / 128), 256, mma_smem>>>(p_atth, wl + WT_OUT,
                                                         out_proj_b + l * W, p_xd,
                                                         p_xd, nullptr,
                                                         256, 256, 0, 1, 0);
        k_ln<<<MROWS, 256>>>(norm2_s + l * W, norm2_b + l * W);
        k_gemm_h<<<dim3(8, MPAD / 128), 256, mma_smem>>>(p_h1h, wl + WT_FF1,
                                                         ff_b1 + l * DFF, nullptr,
                                                         nullptr, p_ffh,
                                                         256, 1024, 1, 0, 1);
        k_gemm_h<<<dim3(2, MPAD / 128), 256, mma_smem>>>(p_ffh, wl + WT_FF2,
                                                         ff_b2 + l * W, p_xd,
                                                         p_xd, nullptr,
                                                         1024, 256, 1, 1, 0);
    }

    // decoder on cls rows
    k_dec<<<B_GR, 256>>>(ln_post_s, ln_post_b, dec_w1, dec_b1, dec_w2, dec_b2,
                         dec_w3, dec_b3, out);
    (void)in_sizes; (void)n_in; (void)out_size;
}

// round 8
// speedup vs baseline: 4.4220x; 1.0218x over previous
#include <cuda_runtime.h>
#include <cuda_fp16.h>
#include <math.h>
#include <stdint.h>

// ---------------- problem constants ----------------
#define N_NODES 16384
#define B_GR    64
#define NPG     256
#define E_EDGES 524288
#define F_IN    32
#define D_IN    56        // 32 + 3*8
#define W       256
#define S       257
#define HEADS   8
#define DH      32
#define DFF     1024
#define HID     512
#define OUT_D   64
#define LAYERS  2
#define MROWS   (B_GR * S)   // 16448
#define MPAD    16512        // 129 * 128

// ---------------- scratch (device globals; no allocs) ----------------
// g_deg and g_agg rely on zero-state: zeroed at module load, and re-zeroed by
// k_gcn after consumption on every run (state-restoring for graph replay).
__device__ float  g_xc  [N_NODES * D_IN];
__device__ float  g_agg [N_NODES * D_IN];
__device__ float  g_deg [N_NODES];
__device__ float  g_xd  [MPAD * W];
__device__ float  g_qkv [MPAD * 3 * W];
__device__ __half g_h1h [MPAD * W];
__device__ __half g_atth[MPAD * W];
__device__ __half g_ffh [MPAD * DFF];
// transposed weights (half): per layer qkvT(768*256) outT(256*256) ff1T(1024*256) ff2T(256*1024)
#define WT_LAYER 786432
#define WT_QKV   0
#define WT_OUT   196608
#define WT_FF1   262144
#define WT_FF2   524288
__device__ __half g_wth[2 * WT_LAYER];

// ---------------- helpers ----------------
__device__ __forceinline__ float warp_sum(float v) {
#pragma unroll
    for (int o = 16; o > 0; o >>= 1) v += __shfl_xor_sync(0xffffffffu, v, o);
    return v;
}
__device__ __forceinline__ float block_sum256(float v, float* red) {
    __syncthreads();
    v = warp_sum(v);
    if ((threadIdx.x & 31) == 0) red[threadIdx.x >> 5] = v;
    __syncthreads();
    float r = 0.f;
#pragma unroll
    for (int i = 0; i < 8; i++) r += red[i];
    return r;
}
__device__ __forceinline__ float gelu_f(float x) {
    float u = 0.7978845608028654f * (x + 0.044715f * x * x * x);
    float t;
    asm("tanh.approx.f32 %0, %1;" : "=f"(t) : "f"(u));
    return 0.5f * x * (1.0f + t);
}
typedef unsigned long long ull;
__device__ __forceinline__ ull ffma2(ull a, ull b, ull c) {
    ull d;
    asm("fma.rn.f32x2 %0, %1, %2, %3;" : "=l"(d) : "l"(a), "l"(b), "l"(c));
    return d;
}
__device__ __forceinline__ ull mul2(ull a, ull b) {
    ull d;
    asm("mul.rn.f32x2 %0, %1, %2;" : "=l"(d) : "l"(a), "l"(b));
    return d;
}
__device__ __forceinline__ ull pack2(float x) {
    ull d;
    asm("mov.b64 %0, {%1, %1};" : "=l"(d) : "f"(x));
    return d;
}
__device__ __forceinline__ float lo2(ull v) { return __uint_as_float((unsigned)(v & 0xffffffffull)); }
__device__ __forceinline__ float hi2(ull v) { return __uint_as_float((unsigned)(v >> 32)); }

__device__ __forceinline__ uint32_t s2u(const void* p) {
    uint32_t a;
    asm("{ .reg .u64 t; cvta.to.shared.u64 t, %1; cvt.u32.u64 %0, t; }" : "=r"(a) : "l"(p));
    return a;
}
__device__ __forceinline__ void cp16(uint32_t dst, const void* src) {
    asm volatile("cp.async.cg.shared.global [%0], [%1], 16;" :: "r"(dst), "l"(src));
}
__device__ __forceinline__ void cp_commit() { asm volatile("cp.async.commit_group;" ::: "memory"); }
__device__ __forceinline__ void cp_wait1()  { asm volatile("cp.async.wait_group 1;" ::: "memory"); }

__device__ __forceinline__ void mma_f16(float* d, const uint32_t* a, const uint32_t* b) {
    asm volatile(
        "mma.sync.aligned.m16n8k16.row.col.f32.f16.f16.f32 "
        "{%0,%1,%2,%3}, {%4,%5,%6,%7}, {%8,%9}, {%0,%1,%2,%3};"
        : "+f"(d[0]), "+f"(d[1]), "+f"(d[2]), "+f"(d[3])
        : "r"(a[0]), "r"(a[1]), "r"(a[2]), "r"(a[3]), "r"(b[0]), "r"(b[1]));
}
__device__ __forceinline__ void ldsm4(uint32_t* r, uint32_t addr) {
    asm volatile("ldmatrix.sync.aligned.m8n8.x4.shared.b16 {%0,%1,%2,%3}, [%4];"
                 : "=r"(r[0]), "=r"(r[1]), "=r"(r[2]), "=r"(r[3]) : "r"(addr));
}
__device__ __forceinline__ void red4(float* addr, float4 v) {
    asm volatile("red.global.add.v4.f32 [%0], {%1,%2,%3,%4};"
                 :: "l"(addr), "f"(v.x), "f"(v.y), "f"(v.z), "f"(v.w) : "memory");
}

// ---------------- fused front-end #1: PE + weight transposes + degree count ----
#define PE_BLOCKS 3584   // N_NODES * D_IN / 256
#define TR_BLOCKS 1536   // 2 layers * 768 tiles
#define DEG_BLOCKS 2048  // E / 256
__global__ void __launch_bounds__(256) k_pe_tr(const float* __restrict__ x,
                                               const float* __restrict__ p,
                                               const int* __restrict__ ei,
                                               const float* __restrict__ ipw,
                                               const float* __restrict__ opw,
                                               const float* __restrict__ f1w,
                                               const float* __restrict__ f2w) {
    if (blockIdx.x < PE_BLOCKS) {
        int i = blockIdx.x * 256 + threadIdx.x;
        int n = i / D_IN, j = i - n * D_IN;
        float v;
        if (j < F_IN) {
            v = x[n * F_IN + j];
        } else {
            int jj = j - F_IN;
            int d = jj >> 3, f = jj & 7;
            float freq = 3.14159265358979323846f * (float)(1 << f);
            v = sinf(p[n * 3 + d] * freq);
        }
        g_xc[i] = v;
        return;
    }
    if (blockIdx.x >= PE_BLOCKS + TR_BLOCKS) {
        // degree count: g_deg starts at 0 (zeroed by k_gcn of previous run)
        int e = (blockIdx.x - PE_BLOCKS - TR_BLOCKS) * 256 + threadIdx.x;
        atomicAdd(&g_deg[ei[E_EDGES + e]], 1.0f);
        return;
    }
    // transpose part: dst[N,K] = half(src[K,N]^T)
    int b2 = blockIdx.x - PE_BLOCKS;
    int layer = b2 / 768;
    int r = b2 - layer * 768;
    const float* src;
    __half* dst;
    int K, N, tile, nx;
    if (r < 192)      { src = ipw + (size_t)layer * W * 768;  dst = g_wth + (size_t)layer * WT_LAYER + WT_QKV; K = 256; N = 768;  tile = r;       nx = 24; }
    else if (r < 256) { src = opw + (size_t)layer * W * W;    dst = g_wth + (size_t)layer * WT_LAYER + WT_OUT; K = 256; N = 256;  tile = r - 192; nx = 8;  }
    else if (r < 512) { src = f1w + (size_t)layer * W * DFF;  dst = g_wth + (size_t)layer * WT_LAYER + WT_FF1; K = 256; N = 1024; tile = r - 256; nx = 32; }
    else              { src = f2w + (size_t)layer * DFF * W;  dst = g_wth + (size_t)layer * WT_LAYER + WT_FF2; K = 1024; N = 256; tile = r - 512; nx = 8;  }
    int bx = (tile % nx) * 32, by = (tile / nx) * 32;
    __shared__ float tl[32][33];
    int tx = threadIdx.x & 31, ty = threadIdx.x >> 5;  // 32x8
#pragma unroll
    for (int j = 0; j < 32; j += 8)
        tl[ty + j][tx] = src[(size_t)(by + ty + j) * N + bx + tx];
    __syncthreads();
#pragma unroll
    for (int j = 0; j < 32; j += 8)
        dst[(size_t)(bx + ty + j) * K + by + tx] = __float2half_rn(tl[tx][ty + j]);
}

// ---------------- front-end #2: edge scatter (g_agg starts at 0) ----------------
// one edge handled by 16 threads (14 active), float4 vector reductions
__global__ void k_scatter(const int* __restrict__ ei) {
    int i = blockIdx.x * blockDim.x + threadIdx.x;  // E*16 total
    int e = i >> 4, j = i & 15;
    if (j >= 14) return;
    int r = ei[e];
    int c = ei[E_EDGES + e];
    float coef = rsqrtf(1.0f + g_deg[r]) * rsqrtf(1.0f + g_deg[c]);
    float4 v = *((const float4*)g_xc + (size_t)r * 14 + j);
    v.x *= coef; v.y *= coef; v.z *= coef; v.w *= coef;
    red4(g_agg + (size_t)c * D_IN + j * 4, v);
}

// ---------------- front-end #3: GCN matvec + ln_pre + layer0 norm1 LN ----------
// also restores zero-state of g_agg and g_deg for the next graph replay.
__global__ void __launch_bounds__(256) k_gcn(const float* __restrict__ w,
                                             const float* __restrict__ bias,
                                             const float* __restrict__ cls_tok,
                                             const float* __restrict__ lns,
                                             const float* __restrict__ lnb,
                                             const float* __restrict__ n1s,
                                             const float* __restrict__ n1b) {
    int blk = blockIdx.x;
    int t = threadIdx.x;
    __shared__ float a[D_IN];
    __shared__ float red[8];
    float acc;
    size_t dst;
    if (blk < N_NODES) {
        int n = blk;
        if (t < D_IN) {
            float dinv2 = 1.0f / (1.0f + g_deg[n]);     // self-loop term
            a[t] = g_agg[n * D_IN + t] + dinv2 * g_xc[n * D_IN + t];
        }
        __syncthreads();
        // restore zero-state for next run
        if (t < D_IN) g_agg[n * D_IN + t] = 0.f;
        if (t == D_IN) g_deg[n] = 0.f;
        acc = bias[t];
#pragma unroll
        for (int i = 0; i < D_IN; i++) acc += a[i] * w[i * W + t];
        int b = n / NPG, pos = n - b * NPG;
        dst = (size_t)(b * S + pos + 1) * W + t;
    } else {
        acc = cls_tok[t];
        dst = (size_t)(blk - N_NODES) * S * W + t;
    }
    float s1 = block_sum256(acc, red);
    float s2 = block_sum256(acc * acc, red);
    float m = s1 * (1.0f / W);
    float var = s2 * (1.0f / W) - m * m;
    float o = (acc - m) * rsqrtf(var + 1e-5f) * lns[t] + lnb[t];
    g_xd[dst] = o;
    // layer-0 norm1 LN fused
    float t1 = block_sum256(o, red);
    float t2 = block_sum256(o * o, red);
    float mb = t1 * (1.0f / W);
    float vb = t2 * (1.0f / W) - mb * mb;
    g_h1h[dst] = __float2half_rn((o - mb) * rsqrtf(vb + 1e-5f) * n1s[t] + n1b[t]);
}

// ---------------- LayerNorm rows: g_xd -> g_h1h (half) ----------------
__global__ void __launch_bounds__(256) k_ln(const float* __restrict__ s,
                                            const float* __restrict__ b) {
    int row = blockIdx.x, t = threadIdx.x;
    __shared__ float red[8];
    float v = g_xd[(size_t)row * W + t];
    float s1 = block_sum256(v, red);
    float s2 = block_sum256(v * v, red);
    float m = s1 * (1.0f / W);
    float var = s2 * (1.0f / W) - m * m;
    g_h1h[(size_t)row * W + t] = __float2half_rn((v - m) * rsqrtf(var + 1e-5f) * s[t] + b[t]);
}

// ---------------- fp16 mma.sync GEMM with ldmatrix fragments ----------------
// C[M,N] = [Res +] act(A[M,K] * Bt[N,K]^T + bias), A/Bt half, fp32 accum.
// Tiles 128x128, Kc=64, 256 threads = 8 warps (4m x 2n), warp tile 32x64,
// per kk(=k16) 2x8 mma(m16n8k16). smem: A[2][128][72]h, B[2][128][72]h = 73728 B.
#define KCH 64
#define SRH 72
__device__ __forceinline__ void hload(uint32_t smb, const __half* A, const __half* Bt,
                                      int bm, int bn, int K, int s, int b, int t) {
    int k0 = s * KCH;
    const __half* Ag = A + (size_t)bm * K + k0;
    const __half* Bg = Bt + (size_t)bn * K + k0;
    uint32_t ab = smb + (uint32_t)b * 18432u;
    uint32_t bb = smb + 36864u + (uint32_t)b * 18432u;
#pragma unroll
    for (int i = 0; i < 4; i++) {
        int q = t + i * 256;          // 0..1023
        int row = q >> 3, c = q & 7;
        uint32_t off = (uint32_t)(row * 144 + c * 16);
        size_t g = (size_t)row * K + c * 8;
        cp16(ab + off, Ag + g);
        cp16(bb + off, Bg + g);
    }
}

__global__ void __launch_bounds__(256, 2) k_gemm_h(const __half* __restrict__ A,
                                                   const __half* __restrict__ Bt,
                                                   const float* __restrict__ bias,
                                                   const float* __restrict__ Res,
                                                   float* __restrict__ Cf,
                                                   __half* __restrict__ Ch,
                                                   int K, int Nn, int act, int has_res,
                                                   int out_half) {
    extern __shared__ __align__(16) char smc[];
    uint32_t smb = s2u(smc);
    int bm = blockIdx.y * 128, bn = blockIdx.x * 128;
    int t = threadIdx.x;
    int wid = t >> 5, lane = t & 31;
    int g = lane >> 2, tig = lane & 3;
    int wm = wid & 3, wn = wid >> 2;          // 4 x 2 warp grid

    float acc[2][8][4];
#pragma unroll
    for (int mt = 0; mt < 2; mt++)
#pragma unroll
        for (int nt = 0; nt < 8; nt++)
#pragma unroll
            for (int i = 0; i < 4; i++) acc[mt][nt][i] = 0.f;

    // ldmatrix per-thread address offsets (bytes, within a buffer)
    uint32_t aoff = (uint32_t)(((wm * 32 + (lane & 15)) * SRH + (lane >> 4) * 8) * 2);
    uint32_t boff = (uint32_t)(((wn * 64 + (lane >> 4) * 8 + (lane & 7)) * SRH +
                                ((lane >> 3) & 1) * 8) * 2);

    const int T = K / KCH;
    hload(smb, A, Bt, bm, bn, K, 0, 0, t);
    cp_commit();
    hload(smb, A, Bt, bm, bn, K, 1, 1, t);
    cp_commit();

    for (int s = 0; s < T; s++) {
        int b = s & 1;
        cp_wait1();
        __syncthreads();
        uint32_t aB = smb + (uint32_t)b * 18432u + aoff;
        uint32_t bB = smb + 36864u + (uint32_t)b * 18432u + boff;
#pragma unroll
        for (int kk = 0; kk < 4; kk++) {
            uint32_t kby = (uint32_t)(kk * 32);
            uint32_t afr[2][4];
            ldsm4(afr[0], aB + kby);
            ldsm4(afr[1], aB + 2 * 16 * SRH + kby);
            uint32_t bfr[4][4];
#pragma unroll
            for (int pp = 0; pp < 4; pp++)
                ldsm4(bfr[pp], bB + (uint32_t)(pp * 16 * SRH * 2) + kby);
#pragma unroll
            for (int mt = 0; mt < 2; mt++)
#pragma unroll
                for (int nt = 0; nt < 8; nt++)
                    mma_f16(acc[mt][nt], afr[mt], &bfr[nt >> 1][(nt & 1) * 2]);
        }
        __syncthreads();
        if (s + 2 < T) hload(smb, A, Bt, bm, bn, K, s + 2, b, t);
        cp_commit();
    }

    // epilogue: rows bm + wm*32 + mt*16 + g (+8), cols bn + wn*64 + nt*8 + 2*tig
#pragma unroll
    for (int mt = 0; mt < 2; mt++) {
        int row0 = bm + wm * 32 + mt * 16 + g;
#pragma unroll
        for (int nt = 0; nt < 8; nt++) {
            int col = bn + wn * 64 + nt * 8 + 2 * tig;
            float2 bb = *(const float2*)&bias[col];
#pragma unroll
            for (int h = 0; h < 2; h++) {
                int row = row0 + h * 8;
                float v0 = acc[mt][nt][2 * h + 0] + bb.x;
                float v1 = acc[mt][nt][2 * h + 1] + bb.y;
                if (act == 1) { v0 = gelu_f(v0); v1 = gelu_f(v1); }
                if (has_res) {
                    float2 r = *(const float2*)&Res[(size_t)row * Nn + col];
                    v0 += r.x; v1 += r.y;
                }
                if (out_half) {
                    *(__half2*)&Ch[(size_t)row * Nn + col] =
                        __floats2half2_rn(v0, v1);
                } else {
                    *(float2*)&Cf[(size_t)row * Nn + col] = make_float2(v0, v1);
                }
            }
        }
    }
}

// ---------------- attention: one thread = one query row, flash-style ----------------
__global__ void __launch_bounds__(288) k_attn() {
    extern __shared__ float sm[];
    float* Ks = sm;            // S*32
    float* Vs = sm + S * DH;   // S*32

    int bh = blockIdx.x;
    int b = bh >> 3, h = bh & 7;
    int t = threadIdx.x;
    const float* base = g_qkv + (size_t)b * S * 768;

    for (int idx = t; idx < S * 8; idx += 288) {
        int s_ = idx >> 3, d4 = idx & 7;
        const float* src = base + (size_t)s_ * 768 + h * 32 + d4 * 4;
        ((float4*)Ks)[idx] = *(const float4*)(src + 256);
        ((float4*)Vs)[idx] = *(const float4*)(src + 512);
    }
    __syncthreads();
    if (t > 256) return;

    int q = t;
    ull qv[16];
    {
        const ull* qp = (const ull*)(base + (size_t)q * 768 + h * 32);
#pragma unroll
        for (int i = 0; i < 16; i++) qv[i] = qp[i];
    }
    ull o[16];
#pragma unroll
    for (int i = 0; i < 16; i++) o[i] = 0ull;
    float m = -1e30f, l = 0.f;
    const float scale = 0.17677669529663687f;  // 1/sqrt(32)
    int kmax = (q == 0) ? 256 : q;

    for (int k = 0; k <= kmax; k++) {
        const ull* kr = (const ull*)&Ks[k * DH];
        ull sacc = 0ull;
#pragma unroll
        for (int i = 0; i < 16; i++) sacc = ffma2(qv[i], kr[i], sacc);
        float s = (lo2(sacc) + hi2(sacc)) * scale;
        float mn = fmaxf(m, s);
        float c = __expf(m - mn);
        float e = __expf(s - mn);
        l = l * c + e;
        ull c2 = pack2(c), e2 = pack2(e);
        const ull* vr = (const ull*)&Vs[k * DH];
#pragma unroll
        for (int i = 0; i < 16; i++) o[i] = ffma2(e2, vr[i], mul2(o[i], c2));
        m = mn;
    }
    float inv = 1.0f / l;
    __half* op = g_atth + ((size_t)b * S + q) * W + h * 32;
#pragma unroll
    for (int i = 0; i < 16; i++) {
        *(__half2*)&op[i * 2] = __floats2half2_rn(lo2(o[i]) * inv, hi2(o[i]) * inv);
    }
}

// ---------------- decoder (fused, one block per graph) ----------------
__global__ void __launch_bounds__(256) k_dec(const float* __restrict__ lns,
                                             const float* __restrict__ lnb,
                                             const float* __restrict__ w1,
                                             const float* __restrict__ b1,
                                             const float* __restrict__ w2,
                                             const float* __restrict__ b2,
                                             const float* __restrict__ w3,
                                             const float* __restrict__ b3,
                                             float* __restrict__ outp) {
    int b = blockIdx.x, t = threadIdx.x;
    __shared__ float cls[W];
    __shared__ float h1[HID];
    __shared__ float h2[HID];
    __shared__ float red[8];
    float v = g_xd[(size_t)b * S * W + t];
    float s1 = block_sum256(v, red);
    float s2 = block_sum256(v * v, red);
    float m = s1 * (1.0f / W);
    float var = s2 * (1.0f / W) - m * m;
    cls[t] = (v - m) * rsqrtf(var + 1e-5f) * lns[t] + lnb[t];
    __syncthreads();
    for (int j = t; j < HID; j += 256) {
        float a = b1[j];
#pragma unroll 8
        for (int i = 0; i < W; i++) a += cls[i] * w1[i * HID + j];
        h1[j] = fmaxf(a, 0.f);
    }
    __syncthreads();
    for (int j = t; j < HID; j += 256) {
        float a = b2[j];
#pragma unroll 8
        for (int i = 0; i < HID; i++) a += h1[i] * w2[i * HID + j];
        h2[j] = fmaxf(a, 0.f);
    }
    __syncthreads();
    if (t < OUT_D) {
        float a = b3[t];
#pragma unroll 8
        for (int i = 0; i < HID; i++) a += h2[i] * w3[i * OUT_D + t];
        outp[b * OUT_D + t] = fmaxf(a, 0.f);
    }
}

// ---------------- launch ----------------
extern "C" void kernel_launch(void* const* d_in, const int* in_sizes, int n_in,
                              void* d_out, int out_size) {
    const float* x          = (const float*)d_in[0];
    const float* p          = (const float*)d_in[1];
    const int*   edge_index = (const int*)d_in[2];
    // d_in[3] = batch (structure known: arange(N)//NPG) — unused
    const float* gcn_w      = (const float*)d_in[4];
    const float* gcn_b      = (const float*)d_in[5];
    const float* cls_token  = (const float*)d_in[6];
    const float* ln_pre_s   = (const float*)d_in[7];
    const float* ln_pre_b   = (const float*)d_in[8];
    const float* norm1_s    = (const float*)d_in[9];
    const float* norm1_b    = (const float*)d_in[10];
    const float* in_proj_w  = (const float*)d_in[11];
    const float* in_proj_b  = (const float*)d_in[12];
    const float* out_proj_w = (const float*)d_in[13];
    const float* out_proj_b = (const float*)d_in[14];
    const float* norm2_s    = (const float*)d_in[15];
    const float* norm2_b    = (const float*)d_in[16];
    const float* ff_w1      = (const float*)d_in[17];
    const float* ff_b1      = (const float*)d_in[18];
    const float* ff_w2      = (const float*)d_in[19];
    const float* ff_b2      = (const float*)d_in[20];
    const float* ln_post_s  = (const float*)d_in[21];
    const float* ln_post_b  = (const float*)d_in[22];
    const float* dec_w1     = (const float*)d_in[23];
    const float* dec_b1     = (const float*)d_in[24];
    const float* dec_w2     = (const float*)d_in[25];
    const float* dec_b2     = (const float*)d_in[26];
    const float* dec_w3     = (const float*)d_in[27];
    const float* dec_b3     = (const float*)d_in[28];
    float* out = (float*)d_out;

    float *p_qkv, *p_xd;
    __half *p_h1h, *p_atth, *p_ffh, *p_wth;
    cudaGetSymbolAddress((void**)&p_qkv, g_qkv);
    cudaGetSymbolAddress((void**)&p_xd, g_xd);
    cudaGetSymbolAddress((void**)&p_h1h, g_h1h);
    cudaGetSymbolAddress((void**)&p_atth, g_atth);
    cudaGetSymbolAddress((void**)&p_ffh, g_ffh);
    cudaGetSymbolAddress((void**)&p_wth, g_wth);

    const int attn_smem = 2 * S * DH * 4;  // 65792
    cudaFuncSetAttribute(k_attn, cudaFuncAttributeMaxDynamicSharedMemorySize, attn_smem);
    const int mma_smem = 73728;
    cudaFuncSetAttribute(k_gemm_h, cudaFuncAttributeMaxDynamicSharedMemorySize, mma_smem);

    // front-end: exactly 3 launches before the first GEMM
    k_pe_tr<<<PE_BLOCKS + TR_BLOCKS + DEG_BLOCKS, 256>>>(x, p, edge_index,
                                                         in_proj_w, out_proj_w, ff_w1, ff_w2);
    k_scatter<<<(E_EDGES * 16) / 256, 256>>>(edge_index);
    k_gcn<<<N_NODES + B_GR, 256>>>(gcn_w, gcn_b, cls_token, ln_pre_s, ln_pre_b,
                                   norm1_s, norm1_b);

    // transformer layers
    for (int l = 0; l < LAYERS; l++) {
        __half* wl = p_wth + (size_t)l * WT_LAYER;
        if (l > 0) k_ln<<<MROWS, 256>>>(norm1_s + l * W, norm1_b + l * W);
        k_gemm_h<<<dim3(6, MPAD / 128), 256, mma_smem>>>(p_h1h, wl + WT_QKV,
                                                         in_proj_b + l * 3 * W, nullptr,
                                                         p_qkv, nullptr,
                                                         256, 768, 0, 0, 0);
        k_attn<<<B_GR * HEADS, 288, attn_smem>>>();
        k_gemm_h<<<dim3(2, MPAD / 128), 256, mma_smem>>>(p_atth, wl + WT_OUT,
                                                         out_proj_b + l * W, p_xd,
                                                         p_xd, nullptr,
                                                         256, 256, 0, 1, 0);
        k_ln<<<MROWS, 256>>>(norm2_s + l * W, norm2_b + l * W);
        k_gemm_h<<<dim3(8, MPAD / 128), 256, mma_smem>>>(p_h1h, wl + WT_FF1,
                                                         ff_b1 + l * DFF, nullptr,
                                                         nullptr, p_ffh,
                                                         256, 1024, 1, 0, 1);
        k_gemm_h<<<dim3(2, MPAD / 128), 256, mma_smem>>>(p_ffh, wl + WT_FF2,
                                                         ff_b2 + l * W, p_xd,
                                                         p_xd, nullptr,
                                                         1024, 256, 1, 1, 0);
    }

    // decoder on cls rows
    k_dec<<<B_GR, 256>>>(ln_post_s, ln_post_b, dec_w1, dec_b1, dec_w2, dec_b2,
                         dec_w3, dec_b3, out);
    (void)in_sizes; (void)n_in; (void)out_size;
}